// round 12
// baseline (speedup 1.0000x reference)
#include <cuda_runtime.h>
#include <cuda_bf16.h>
#include <math_constants.h>
#include <cstdint>

// Problem constants (fixed dataset shapes)
#define NMAX 20000
#define EMAX 320000
#define ETOT (EMAX + NMAX)

// ---------------- device scratch (static allocations only) ----------------
__device__ float g_h1[(size_t)NMAX * 128];
__device__ float g_h2[(size_t)NMAX * 128];
__device__ float g_xlxr[(size_t)NMAX * 1024];    // layer1 & actor: [xl(512) | xr(512)]
__device__ float g_xlxr2[(size_t)NMAX * 1024];   // critic
__device__ int   g_cnt[NMAX];
__device__ int   g_rp[NMAX + 1];
__device__ int   g_cur[NMAX];
__device__ int   g_csrc[ETOT];

// bf16 hi/lo activations
__device__ __nv_bfloat16 g_ahi[(size_t)NMAX * 128];
__device__ __nv_bfloat16 g_alo[(size_t)NMAX * 128];
// transposed bf16 hi/lo weights: rows = 128(W_in) + 6*512 = 3200, each row 128 bf16
#define WT_ROWS 3200
__device__ __nv_bfloat16 g_wthi[(size_t)WT_ROWS * 128];
__device__ __nv_bfloat16 g_wtlo[(size_t)WT_ROWS * 128];
// packed biases, index-matched to wt rows
__device__ float g_biasc[WT_ROWS];

// ---------------- CSR build ----------------
__global__ void count_k(const int* __restrict__ dstv, int E) {
    int i = blockIdx.x * blockDim.x + threadIdx.x;
    if (i < E) atomicAdd(&g_cnt[dstv[i]], 1);
}
__global__ void scan2_k(int N) {
    __shared__ int wsum[32];
    int tid = threadIdx.x;
    int lane = tid & 31, wid = tid >> 5;
    int per = (N + 1023) >> 10;
    int start = tid * per;
    int s = 0;
    for (int i = 0; i < per; ++i) {
        int idx = start + i;
        if (idx < N) s += g_cnt[idx];
    }
    int v = s;
    #pragma unroll
    for (int off = 1; off < 32; off <<= 1) {
        int t = __shfl_up_sync(0xffffffffu, v, off);
        if (lane >= off) v += t;
    }
    if (lane == 31) wsum[wid] = v;
    __syncthreads();
    if (wid == 0) {
        int w = wsum[lane];
        #pragma unroll
        for (int off = 1; off < 32; off <<= 1) {
            int t = __shfl_up_sync(0xffffffffu, w, off);
            if (lane >= off) w += t;
        }
        wsum[lane] = w;
    }
    __syncthreads();
    int excl = v - s + (wid ? wsum[wid - 1] : 0);
    int run = excl;
    for (int i = 0; i < per; ++i) {
        int idx = start + i;
        if (idx < N) {
            int c = g_cnt[idx];
            g_cur[idx] = run;
            run += c;
            g_rp[idx + 1] = run;
        }
    }
    if (tid == 0) g_rp[0] = 0;
}
__global__ void scatter_k(const int* __restrict__ srcv, const int* __restrict__ dstv,
                          int E, int N) {
    int i = blockIdx.x * blockDim.x + threadIdx.x;
    if (i < E) {
        int d = dstv[i];
        int pos = atomicAdd(&g_cur[d], 1);
        g_csrc[pos] = srcv[i];
    } else if (i < E + N) {
        int n = i - E;
        int pos = atomicAdd(&g_cur[n], 1);
        g_csrc[pos] = n;
    }
}

// ---------------- weights transpose + hi/lo + bias pack + cnt init, ONE launch ----------------
__device__ __forceinline__ uint32_t pack_bf2(__nv_bfloat16 a, __nv_bfloat16 b) {
    return (uint32_t)__bfloat16_as_ushort(a) | ((uint32_t)__bfloat16_as_ushort(b) << 16);
}

__global__ void conv_all_k(const float* __restrict__ w0, const float* __restrict__ w1,
                           const float* __restrict__ w2, const float* __restrict__ w3,
                           const float* __restrict__ w4, const float* __restrict__ w5,
                           const float* __restrict__ w6,
                           const float* __restrict__ b0, const float* __restrict__ b1,
                           const float* __restrict__ b2, const float* __restrict__ b3,
                           const float* __restrict__ b4, const float* __restrict__ b5,
                           const float* __restrict__ b6, int N) {
    int i = blockIdx.x * blockDim.x + threadIdx.x;
    if (i < N) g_cnt[i] = 1;   // self-loop pre-count
    const int WTH = 2048 + 6 * 8192;   // 51200
    if (i < WTH) {
        const float* W; int cols, rowoff, n, kg;
        if (i < 2048) { W = w0; cols = 128; rowoff = 0; n = i & 127; kg = i >> 7; }
        else {
            int j = i - 2048;
            int s = j >> 13;
            int r = j & 8191;
            n = r & 511; kg = r >> 9;
            W = (s == 0) ? w1 : (s == 1) ? w2 : (s == 2) ? w3 : (s == 3) ? w4 : (s == 4) ? w5 : w6;
            cols = 512; rowoff = 128 + s * 512;
        }
        int k0 = kg * 8;
        __nv_bfloat16 h8[8], l8v[8];
        #pragma unroll
        for (int q = 0; q < 8; ++q) {
            float v = W[(size_t)(k0 + q) * cols + n];
            __nv_bfloat16 h = __float2bfloat16(v);
            h8[q] = h;
            l8v[q] = __float2bfloat16(v - __bfloat162float(h));
        }
        uint4 hv, lv;
        hv.x = pack_bf2(h8[0], h8[1]); hv.y = pack_bf2(h8[2], h8[3]);
        hv.z = pack_bf2(h8[4], h8[5]); hv.w = pack_bf2(h8[6], h8[7]);
        lv.x = pack_bf2(l8v[0], l8v[1]); lv.y = pack_bf2(l8v[2], l8v[3]);
        lv.z = pack_bf2(l8v[4], l8v[5]); lv.w = pack_bf2(l8v[6], l8v[7]);
        *(uint4*)(g_wthi + (size_t)(rowoff + n) * 128 + k0) = hv;
        *(uint4*)(g_wtlo + (size_t)(rowoff + n) * 128 + k0) = lv;
    } else if (i < WTH + WT_ROWS) {
        int j = i - WTH;
        float v;
        if (j < 128) v = b0[j];
        else {
            int s = (j - 128) >> 9, t = (j - 128) & 511;
            const float* B = (s == 0) ? b1 : (s == 1) ? b2 : (s == 2) ? b3
                           : (s == 3) ? b4 : (s == 4) ? b5 : b6;
            v = B[t];
        }
        g_biasc[j] = v;
    }
}

// ---------------- activation fp32 -> bf16 hi/lo (x only) ----------------
__global__ void conv_a_k(const float* __restrict__ src, int n4) {
    int i = blockIdx.x * blockDim.x + threadIdx.x;
    if (i < n4) {
        float4 v = ((const float4*)src)[i];
        __nv_bfloat16 hx = __float2bfloat16(v.x);
        __nv_bfloat16 hy = __float2bfloat16(v.y);
        __nv_bfloat16 hz = __float2bfloat16(v.z);
        __nv_bfloat16 hw = __float2bfloat16(v.w);
        __nv_bfloat16 lx = __float2bfloat16(v.x - __bfloat162float(hx));
        __nv_bfloat16 ly = __float2bfloat16(v.y - __bfloat162float(hy));
        __nv_bfloat16 lz = __float2bfloat16(v.z - __bfloat162float(hz));
        __nv_bfloat16 lw = __float2bfloat16(v.w - __bfloat162float(hw));
        ((uint2*)g_ahi)[i] = make_uint2(pack_bf2(hx, hy), pack_bf2(hz, hw));
        ((uint2*)g_alo)[i] = make_uint2(pack_bf2(lx, ly), pack_bf2(lz, lw));
    }
}

// ======== bf16x3 GEMM v4: persistent col tile, double-buffered A, 512 threads ========
#define TSTRIDE 272
#define TILE_B (128 * TSTRIDE)
#define GMM_SMEM (6 * TILE_B)

__device__ __forceinline__ uint32_t smem_u32(const void* p) {
    uint32_t a;
    asm("{ .reg .u64 t; cvta.to.shared.u64 t, %1; cvt.u32.u64 %0, t; }" : "=r"(a) : "l"(p));
    return a;
}

#define CP16(dst, src, sz) \
    asm volatile("cp.async.cg.shared.global [%0], [%1], 16, %2;" \
                 :: "r"(dst), "l"(src), "r"(sz) : "memory")
#define CP_COMMIT() asm volatile("cp.async.commit_group;" ::: "memory")
#define CP_WAIT0()  asm volatile("cp.async.wait_group 0;" ::: "memory")
#define CP_WAIT1()  asm volatile("cp.async.wait_group 1;" ::: "memory")

#define LDMX4(r0, r1, r2, r3, addr) \
    asm volatile("ldmatrix.sync.aligned.m8n8.x4.shared.b16 {%0,%1,%2,%3}, [%4];" \
                 : "=r"(r0), "=r"(r1), "=r"(r2), "=r"(r3) : "r"(addr))

#define MMA_BF16(c, a0, a1, a2, a3, b0, b1) \
    asm volatile("mma.sync.aligned.m16n8k16.row.col.f32.bf16.bf16.f32 " \
                 "{%0,%1,%2,%3}, {%4,%5,%6,%7}, {%8,%9}, {%0,%1,%2,%3};" \
                 : "+f"((c)[0]), "+f"((c)[1]), "+f"((c)[2]), "+f"((c)[3]) \
                 : "r"(a0), "r"(a1), "r"(a2), "r"(a3), "r"(b0), "r"(b1))

__device__ __forceinline__ void prefetch_A(uint32_t uAhi, uint32_t uAlo,
                                           const __nv_bfloat16* Ahi, const __nv_bfloat16* Alo,
                                           int row0, int M, int tid) {
    #pragma unroll
    for (int it = 0; it < 4; ++it) {
        int idx = it * 512 + tid;
        int row = idx >> 4, c = idx & 15;
        int grow = row0 + row;
        int ok = grow < M;
        int srow = ok ? grow : 0;
        uint32_t sz = ok ? 16u : 0u;
        CP16(uAhi + row * TSTRIDE + c * 16,
             (const char*)(Ahi + (size_t)srow * 128) + c * 16, sz);
        CP16(uAlo + row * TSTRIDE + c * 16,
             (const char*)(Alo + (size_t)srow * 128) + c * 16, sz);
    }
}

__global__ void __launch_bounds__(512, 1)
gemm_mma_k(const __nv_bfloat16* __restrict__ Ahi, const __nv_bfloat16* __restrict__ Alo, int M,
           const __nv_bfloat16* __restrict__ Bhi, const __nv_bfloat16* __restrict__ Blo,
           const float* __restrict__ bias,
           float* __restrict__ out, float* __restrict__ out2, int split,
           int ldo, int do_relu, int conv_out) {
    extern __shared__ char sm[];
    char* sBhi = sm;
    char* sBlo = sm + TILE_B;
    char* sA[2][2];
    sA[0][0] = sm + 2 * TILE_B;
    sA[0][1] = sm + 3 * TILE_B;
    sA[1][0] = sm + 4 * TILE_B;
    sA[1][1] = sm + 5 * TILE_B;

    int tid = threadIdx.x;
    int wc0 = blockIdx.y * 128;
    int oc  = wc0;
    if (oc >= split) { out = out2; oc -= split; }

    uint32_t uBhi = smem_u32(sBhi), uBlo = smem_u32(sBlo);
    uint32_t uA[2][2];
    #pragma unroll
    for (int s = 0; s < 2; ++s) { uA[s][0] = smem_u32(sA[s][0]); uA[s][1] = smem_u32(sA[s][1]); }

    #pragma unroll
    for (int it = 0; it < 4; ++it) {
        int idx = it * 512 + tid;
        int row = idx >> 4, c = idx & 15;
        CP16(uBhi + row * TSTRIDE + c * 16,
             (const char*)(Bhi + (size_t)(wc0 + row) * 128) + c * 16, 16u);
        CP16(uBlo + row * TSTRIDE + c * 16,
             (const char*)(Blo + (size_t)(wc0 + row) * 128) + c * 16, 16u);
    }
    int nrt = (M + 127) >> 7;
    int stride = gridDim.x;
    int r0 = blockIdx.x;
    if (r0 < nrt)
        prefetch_A(uA[0][0], uA[0][1], Ahi, Alo, r0 * 128, M, tid);
    CP_COMMIT();

    int wid = tid >> 5;
    int lane = tid & 31;
    int m0 = (wid & 3) * 32;
    int n0 = (wid >> 2) * 32;

    int gq = lane >> 3, l8 = lane & 7;
    int fr_row = (gq & 1) * 8 + l8;
    int fr_col = (gq >> 1) * 16;

    uint32_t aoff[2], boff[2];
    #pragma unroll
    for (int mt = 0; mt < 2; ++mt)
        aoff[mt] = (uint32_t)((m0 + mt * 16 + fr_row) * TSTRIDE + fr_col);
    #pragma unroll
    for (int nt2 = 0; nt2 < 2; ++nt2)
        boff[nt2] = (uint32_t)((n0 + nt2 * 16 + fr_row) * TSTRIDE + fr_col);

    int qr = lane >> 2;
    int qc = (lane & 3) * 2;
    float2 bv[4];
    #pragma unroll
    for (int nt = 0; nt < 4; ++nt)
        bv[nt] = *(const float2*)(bias + wc0 + n0 + nt * 8 + qc);

    int buf = 0;
    for (int r = r0; r < nrt; r += stride) {
        int rn = r + stride;
        if (rn < nrt)
            prefetch_A(uA[buf ^ 1][0], uA[buf ^ 1][1], Ahi, Alo, rn * 128, M, tid);
        CP_COMMIT();
        if (rn < nrt) CP_WAIT1(); else CP_WAIT0();
        __syncthreads();

        uint32_t uAhi = uA[buf][0], uAlo = uA[buf][1];

        float c[2][4][4];
        #pragma unroll
        for (int mt = 0; mt < 2; ++mt)
            #pragma unroll
            for (int nt = 0; nt < 4; ++nt)
                #pragma unroll
                for (int q = 0; q < 4; ++q) c[mt][nt][q] = 0.f;

        #pragma unroll
        for (int kk = 0; kk < 8; ++kk) {
            uint32_t ah[2][4], al2[2][4];
            #pragma unroll
            for (int mt = 0; mt < 2; ++mt) {
                LDMX4(ah[mt][0], ah[mt][1], ah[mt][2], ah[mt][3], uAhi + aoff[mt] + kk * 32);
                LDMX4(al2[mt][0], al2[mt][1], al2[mt][2], al2[mt][3], uAlo + aoff[mt] + kk * 32);
            }
            uint32_t bh[2][4], bl[2][4];
            #pragma unroll
            for (int nt2 = 0; nt2 < 2; ++nt2) {
                LDMX4(bh[nt2][0], bh[nt2][1], bh[nt2][2], bh[nt2][3], uBhi + boff[nt2] + kk * 32);
                LDMX4(bl[nt2][0], bl[nt2][1], bl[nt2][2], bl[nt2][3], uBlo + boff[nt2] + kk * 32);
            }
            #pragma unroll
            for (int mt = 0; mt < 2; ++mt)
                #pragma unroll
                for (int nt = 0; nt < 4; ++nt) {
                    int nt2 = nt >> 1, odd = nt & 1;
                    MMA_BF16(c[mt][nt], ah[mt][0], ah[mt][1], ah[mt][2], ah[mt][3],
                             bh[nt2][odd], bh[nt2][2 + odd]);
                    MMA_BF16(c[mt][nt], ah[mt][0], ah[mt][1], ah[mt][2], ah[mt][3],
                             bl[nt2][odd], bl[nt2][2 + odd]);
                    MMA_BF16(c[mt][nt], al2[mt][0], al2[mt][1], al2[mt][2], al2[mt][3],
                             bh[nt2][odd], bh[nt2][2 + odd]);
                }
        }

        int row0 = r * 128;
        #pragma unroll
        for (int mt = 0; mt < 2; ++mt) {
            int r_lo = row0 + m0 + mt * 16 + qr;
            #pragma unroll
            for (int nt = 0; nt < 4; ++nt) {
                int colb = n0 + nt * 8 + qc;
                float2 v0 = make_float2(c[mt][nt][0] + bv[nt].x, c[mt][nt][1] + bv[nt].y);
                float2 v1 = make_float2(c[mt][nt][2] + bv[nt].x, c[mt][nt][3] + bv[nt].y);
                if (do_relu) {
                    v0.x = fmaxf(v0.x, 0.f); v0.y = fmaxf(v0.y, 0.f);
                    v1.x = fmaxf(v1.x, 0.f); v1.y = fmaxf(v1.y, 0.f);
                }
                #pragma unroll
                for (int half = 0; half < 2; ++half) {
                    int rr = r_lo + half * 8;
                    float2 vv = half ? v1 : v0;
                    if (rr < M) {
                        *(float2*)(out + (size_t)rr * ldo + oc + colb) = vv;
                        if (conv_out) {
                            __nv_bfloat16 hx = __float2bfloat16(vv.x);
                            __nv_bfloat16 hy = __float2bfloat16(vv.y);
                            __nv_bfloat16 lx = __float2bfloat16(vv.x - __bfloat162float(hx));
                            __nv_bfloat16 ly = __float2bfloat16(vv.y - __bfloat162float(hy));
                            size_t ai = (size_t)rr * 128 + oc + colb;
                            *(uint32_t*)(g_ahi + ai) = pack_bf2(hx, hy);
                            *(uint32_t*)(g_alo + ai) = pack_bf2(lx, ly);
                        }
                    }
                }
            }
        }
        __syncthreads();
        buf ^= 1;
    }
}

// ===== GATv2: one node per 64-thread block, 2 warps split the edge list =====
#define LRD(t, x4, r4, a4) do {                                        \
    float ex = (x4).x + (r4).x; ex = fmaxf(ex, 0.2f * ex); t = fmaf(ex, (a4).x, t); \
    float ey = (x4).y + (r4).y; ey = fmaxf(ey, 0.2f * ey); t = fmaf(ey, (a4).y, t); \
    float ez = (x4).z + (r4).z; ez = fmaxf(ez, 0.2f * ez); t = fmaf(ez, (a4).z, t); \
    float ew = (x4).w + (r4).w; ew = fmaxf(ew, 0.2f * ew); t = fmaf(ew, (a4).w, t); \
} while (0)

template <int WRITE_H>
__global__ void __launch_bounds__(64)
gat3_k(const float* __restrict__ xlxr,
       const float* __restrict__ hres,
       const float* __restrict__ att,
       const float* __restrict__ gatb,
       const float* __restrict__ lng,
       const float* __restrict__ lnb,
       const float* __restrict__ headW,
       const float* __restrict__ headb,
       float* __restrict__ outh,
       float* __restrict__ outsc,
       int N) {
    __shared__ float sm_m[32], sm_d[32], sm_acc[32][16];

    int n    = blockIdx.x;
    int warp = threadIdx.x >> 5;
    int lane = threadIdx.x & 31;
    if (n >= N) return;
    int g  = lane >> 3;
    int l8 = lane & 7;
    int cb = g * 32 + l8 * 4;

    float4 atv[4], xrv[4];
    const float4* ap = (const float4*)att + cb;
    const float4* xp = (const float4*)(xlxr + (size_t)n * 1024 + 512) + cb;
    #pragma unroll
    for (int j = 0; j < 4; ++j) { atv[j] = ap[j]; xrv[j] = xp[j]; }

    float m = -CUDART_INF_F, d = 0.f;
    float4 acc[4];
    #pragma unroll
    for (int j = 0; j < 4; ++j) acc[j] = make_float4(0.f, 0.f, 0.f, 0.f);

    // split this node's edge list between the two warps
    int beg0 = g_rp[n], end0 = g_rp[n + 1];
    int len  = end0 - beg0;
    int half = (len + 1) >> 1;
    int e    = warp ? (beg0 + half) : beg0;
    int end  = warp ? end0 : (beg0 + half);

    for (; e + 2 <= end; e += 2) {
        int s0 = g_csrc[e];
        int s1 = g_csrc[e + 1];
        const float4* q0 = (const float4*)(xlxr + (size_t)s0 * 1024) + cb;
        const float4* q1 = (const float4*)(xlxr + (size_t)s1 * 1024) + cb;
        float4 x0[4], x1[4];
        #pragma unroll
        for (int j = 0; j < 4; ++j) x0[j] = q0[j];
        #pragma unroll
        for (int j = 0; j < 4; ++j) x1[j] = q1[j];

        float t0 = 0.f, t1 = 0.f;
        #pragma unroll
        for (int j = 0; j < 4; ++j) { LRD(t0, x0[j], xrv[j], atv[j]); LRD(t1, x1[j], xrv[j], atv[j]); }
        t0 += __shfl_xor_sync(0xffffffffu, t0, 1);
        t1 += __shfl_xor_sync(0xffffffffu, t1, 1);
        t0 += __shfl_xor_sync(0xffffffffu, t0, 2);
        t1 += __shfl_xor_sync(0xffffffffu, t1, 2);
        t0 += __shfl_xor_sync(0xffffffffu, t0, 4);
        t1 += __shfl_xor_sync(0xffffffffu, t1, 4);

        float mn = fmaxf(m, fmaxf(t0, t1));
        float sc = __expf(m - mn);
        float p0 = __expf(t0 - mn);
        float p1 = __expf(t1 - mn);
        d = fmaf(d, sc, p0 + p1);
        #pragma unroll
        for (int j = 0; j < 4; ++j) {
            acc[j].x = fmaf(acc[j].x, sc, fmaf(p0, x0[j].x, p1 * x1[j].x));
            acc[j].y = fmaf(acc[j].y, sc, fmaf(p0, x0[j].y, p1 * x1[j].y));
            acc[j].z = fmaf(acc[j].z, sc, fmaf(p0, x0[j].z, p1 * x1[j].z));
            acc[j].w = fmaf(acc[j].w, sc, fmaf(p0, x0[j].w, p1 * x1[j].w));
        }
        m = mn;
    }
    if (e < end) {
        int s0 = g_csrc[e];
        const float4* q0 = (const float4*)(xlxr + (size_t)s0 * 1024) + cb;
        float4 x0[4];
        #pragma unroll
        for (int j = 0; j < 4; ++j) x0[j] = q0[j];
        float t0 = 0.f;
        #pragma unroll
        for (int j = 0; j < 4; ++j) LRD(t0, x0[j], xrv[j], atv[j]);
        t0 += __shfl_xor_sync(0xffffffffu, t0, 1);
        t0 += __shfl_xor_sync(0xffffffffu, t0, 2);
        t0 += __shfl_xor_sync(0xffffffffu, t0, 4);
        float mn = fmaxf(m, t0);
        float sc = __expf(m - mn);
        float p0 = __expf(t0 - mn);
        d = fmaf(d, sc, p0);
        #pragma unroll
        for (int j = 0; j < 4; ++j) {
            acc[j].x = fmaf(acc[j].x, sc, p0 * x0[j].x);
            acc[j].y = fmaf(acc[j].y, sc, p0 * x0[j].y);
            acc[j].z = fmaf(acc[j].z, sc, p0 * x0[j].z);
            acc[j].w = fmaf(acc[j].w, sc, p0 * x0[j].w);
        }
        m = mn;
    }

    // ---- merge warp1's partial state into warp0 ----
    float* a = (float*)acc;
    if (warp == 1) {
        sm_m[lane] = m;
        sm_d[lane] = d;
        #pragma unroll
        for (int i = 0; i < 16; ++i) sm_acc[lane][i] = a[i];
    }
    __syncthreads();
    if (warp == 1) return;

    {
        float m1 = sm_m[lane], d1 = sm_d[lane];
        float mn = fmaxf(m, m1);
        float sc0 = __expf(m - mn);
        float sc1 = __expf(m1 - mn);
        d = d * sc0 + d1 * sc1;
        #pragma unroll
        for (int i = 0; i < 16; ++i)
            a[i] = a[i] * sc0 + sm_acc[lane][i] * sc1;
    }

    float inv = 0.25f / d;
    #pragma unroll
    for (int i = 0; i < 16; ++i) {
        float v = a[i] * inv;
        v += __shfl_xor_sync(0xffffffffu, v, 8);
        v += __shfl_xor_sync(0xffffffffu, v, 16);
        a[i] = v;
    }

    int fb = l8 * 4;
    const float4* gbp = (const float4*)gatb + fb;
    const float4* hrp = (const float4*)(hres + (size_t)n * 128) + fb;
    float4 v4[4];
    float s1 = 0.f, s2 = 0.f;
    #pragma unroll
    for (int j = 0; j < 4; ++j) {
        float4 gb = gbp[j], hr = hrp[j];
        v4[j].x = acc[j].x + gb.x + hr.x;
        v4[j].y = acc[j].y + gb.y + hr.y;
        v4[j].z = acc[j].z + gb.z + hr.z;
        v4[j].w = acc[j].w + gb.w + hr.w;
        s1 += v4[j].x + v4[j].y + v4[j].z + v4[j].w;
        s2 += v4[j].x * v4[j].x + v4[j].y * v4[j].y + v4[j].z * v4[j].z + v4[j].w * v4[j].w;
    }
    s1 += __shfl_xor_sync(0xffffffffu, s1, 1);
    s2 += __shfl_xor_sync(0xffffffffu, s2, 1);
    s1 += __shfl_xor_sync(0xffffffffu, s1, 2);
    s2 += __shfl_xor_sync(0xffffffffu, s2, 2);
    s1 += __shfl_xor_sync(0xffffffffu, s1, 4);
    s2 += __shfl_xor_sync(0xffffffffu, s2, 4);
    float mean = s1 * (1.f / 128.f);
    float var  = s2 * (1.f / 128.f) - mean * mean;
    float rstd = rsqrtf(var + 1e-5f);

    const float4* gp = (const float4*)lng + fb;
    const float4* bp = (const float4*)lnb + fb;
    float4 y4[4];
    #pragma unroll
    for (int j = 0; j < 4; ++j) {
        float4 gg = gp[j], bb = bp[j];
        y4[j].x = fmaxf((v4[j].x - mean) * rstd * gg.x + bb.x, 0.f);
        y4[j].y = fmaxf((v4[j].y - mean) * rstd * gg.y + bb.y, 0.f);
        y4[j].z = fmaxf((v4[j].z - mean) * rstd * gg.z + bb.z, 0.f);
        y4[j].w = fmaxf((v4[j].w - mean) * rstd * gg.w + bb.w, 0.f);
    }

    if (WRITE_H) {
        if (g == 0) {
            float4* op = (float4*)outh + (size_t)n * 32 + fb;
            #pragma unroll
            for (int j = 0; j < 4; ++j) {
                op[j] = y4[j];
                __nv_bfloat16 hx = __float2bfloat16(y4[j].x);
                __nv_bfloat16 hy = __float2bfloat16(y4[j].y);
                __nv_bfloat16 hz = __float2bfloat16(y4[j].z);
                __nv_bfloat16 hw = __float2bfloat16(y4[j].w);
                __nv_bfloat16 lx = __float2bfloat16(y4[j].x - __bfloat162float(hx));
                __nv_bfloat16 ly = __float2bfloat16(y4[j].y - __bfloat162float(hy));
                __nv_bfloat16 lz = __float2bfloat16(y4[j].z - __bfloat162float(hz));
                __nv_bfloat16 lw = __float2bfloat16(y4[j].w - __bfloat162float(hw));
                size_t ai = (size_t)n * 32 + fb + j;
                ((uint2*)g_ahi)[ai] = make_uint2(pack_bf2(hx, hy), pack_bf2(hz, hw));
                ((uint2*)g_alo)[ai] = make_uint2(pack_bf2(lx, ly), pack_bf2(lz, lw));
            }
        }
    } else {
        const float4* wp = (const float4*)headW + fb;
        float pp = 0.f;
        #pragma unroll
        for (int j = 0; j < 4; ++j) {
            float4 w4 = wp[j];
            pp = fmaf(y4[j].x, w4.x, pp);
            pp = fmaf(y4[j].y, w4.y, pp);
            pp = fmaf(y4[j].z, w4.z, pp);
            pp = fmaf(y4[j].w, w4.w, pp);
        }
        pp += __shfl_xor_sync(0xffffffffu, pp, 1);
        pp += __shfl_xor_sync(0xffffffffu, pp, 2);
        pp += __shfl_xor_sync(0xffffffffu, pp, 4);
        if (lane == 0) outsc[n] = pp + headb[0];
    }
}

// ---------------- launch ----------------
extern "C" void kernel_launch(void* const* d_in, const int* in_sizes, int n_in,
                              void* d_out, int out_size) {
    const float* x     = (const float*)d_in[0];
    const int*   ei    = (const int*)d_in[1];
    const float* W_in  = (const float*)d_in[2];
    const float* b_in  = (const float*)d_in[3];
    const float* c1_Wl = (const float*)d_in[4];
    const float* c1_bl = (const float*)d_in[5];
    const float* c1_Wr = (const float*)d_in[6];
    const float* c1_br = (const float*)d_in[7];
    const float* c1_att= (const float*)d_in[8];
    const float* c1_b  = (const float*)d_in[9];
    const float* ln1_g = (const float*)d_in[10];
    const float* ln1_b = (const float*)d_in[11];
    const float* a_Wl  = (const float*)d_in[12];
    const float* a_bl  = (const float*)d_in[13];
    const float* a_Wr  = (const float*)d_in[14];
    const float* a_br  = (const float*)d_in[15];
    const float* a_att = (const float*)d_in[16];
    const float* a_b   = (const float*)d_in[17];
    const float* aln_g = (const float*)d_in[18];
    const float* aln_b = (const float*)d_in[19];
    const float* ah_W  = (const float*)d_in[20];
    const float* ah_b  = (const float*)d_in[21];
    const float* k_Wl  = (const float*)d_in[22];
    const float* k_bl  = (const float*)d_in[23];
    const float* k_Wr  = (const float*)d_in[24];
    const float* k_br  = (const float*)d_in[25];
    const float* k_att = (const float*)d_in[26];
    const float* k_b   = (const float*)d_in[27];
    const float* kln_g = (const float*)d_in[28];
    const float* kln_b = (const float*)d_in[29];
    const float* kh_W  = (const float*)d_in[30];
    const float* kh_b  = (const float*)d_in[31];

    int N = in_sizes[0] / 128;
    int E = in_sizes[1] / 2;
    float* out = (float*)d_out;

    float *h1, *h2, *xlxr, *xlxr2, *biasc;
    __nv_bfloat16 *ahi, *alo, *wthi, *wtlo;
    cudaGetSymbolAddress((void**)&h1, g_h1);
    cudaGetSymbolAddress((void**)&h2, g_h2);
    cudaGetSymbolAddress((void**)&xlxr, g_xlxr);
    cudaGetSymbolAddress((void**)&xlxr2, g_xlxr2);
    cudaGetSymbolAddress((void**)&biasc, g_biasc);
    cudaGetSymbolAddress((void**)&ahi, g_ahi);
    cudaGetSymbolAddress((void**)&alo, g_alo);
    cudaGetSymbolAddress((void**)&wthi, g_wthi);
    cudaGetSymbolAddress((void**)&wtlo, g_wtlo);

    cudaFuncSetAttribute(gemm_mma_k, cudaFuncAttributeMaxDynamicSharedMemorySize, GMM_SMEM);

    int gc = (N * 32 + 255) / 256;
    const int NOSPLIT = 1 << 30;

    conv_all_k<<<(2048 + 6 * 8192 + WT_ROWS + 255) / 256, 256>>>(          // 1
        W_in, c1_Wl, c1_Wr, a_Wl, a_Wr, k_Wl, k_Wr,
        b_in, c1_bl, c1_br, a_bl, a_br, k_bl, k_br, N);
    conv_a_k<<<gc, 256>>>(x, N * 32);                                      // 2
    gemm_mma_k<<<dim3(148, 1), 512, GMM_SMEM>>>(ahi, alo, N,               // 3: input layer
        wthi, wtlo, biasc, h1, (float*)0, NOSPLIT, 128, 1, 1);
    gemm_mma_k<<<dim3(18, 8), 512, GMM_SMEM>>>(ahi, alo, N,                // 4 <- profiled
        wthi + (size_t)128 * 128, wtlo + (size_t)128 * 128, biasc + 128,
        xlxr, (float*)0, NOSPLIT, 1024, 0, 0);

    count_k<<<(E + 255) / 256, 256>>>(ei + E, E);                          // 5
    scan2_k<<<1, 1024>>>(N);                                               // 6
    scatter_k<<<(E + N + 255) / 256, 256>>>(ei, ei + E, E, N);             // 7

    gat3_k<1><<<N, 64>>>(xlxr, h1, c1_att, c1_b, ln1_g, ln1_b,             // 8
                         (const float*)0, (const float*)0, h2, (float*)0, N);

    gemm_mma_k<<<dim3(9, 16), 512, GMM_SMEM>>>(ahi, alo, N,                // 9
        wthi + (size_t)1152 * 128, wtlo + (size_t)1152 * 128, biasc + 1152,
        xlxr, xlxr2, 1024, 1024, 0, 0);

    gat3_k<0><<<N, 64>>>(xlxr, h2, a_att, a_b, aln_g, aln_b,               // 10
                         ah_W, ah_b, (float*)0, out, N);
    gat3_k<0><<<N, 64>>>(xlxr2, h2, k_att, k_b, kln_g, kln_b,              // 11
                         kh_W, kh_b, (float*)0, out + N, N);
}

// round 13
// speedup vs baseline: 1.0779x; 1.0779x over previous
#include <cuda_runtime.h>
#include <cuda_bf16.h>
#include <math_constants.h>
#include <cstdint>

// Problem constants (fixed dataset shapes)
#define NMAX 20000
#define EMAX 320000
#define ETOT (EMAX + NMAX)

// ---------------- device scratch (static allocations only) ----------------
__device__ float g_h1[(size_t)NMAX * 128];
__device__ float g_h2[(size_t)NMAX * 128];
__device__ float g_xlxr[(size_t)NMAX * 1024];    // layer1 & actor: [xl(512) | xr(512)]
__device__ float g_xlxr2[(size_t)NMAX * 1024];   // critic
__device__ int   g_cnt[NMAX];
__device__ int   g_rp[NMAX + 1];
__device__ int   g_cur[NMAX];
__device__ int   g_csrc[ETOT];

// bf16 hi/lo activations
__device__ __nv_bfloat16 g_ahi[(size_t)NMAX * 128];
__device__ __nv_bfloat16 g_alo[(size_t)NMAX * 128];
// transposed bf16 hi/lo weights: rows = 128(W_in) + 6*512 = 3200, each row 128 bf16
#define WT_ROWS 3200
__device__ __nv_bfloat16 g_wthi[(size_t)WT_ROWS * 128];
__device__ __nv_bfloat16 g_wtlo[(size_t)WT_ROWS * 128];
// packed biases, index-matched to wt rows
__device__ float g_biasc[WT_ROWS];

// ---------------- CSR build ----------------
__global__ void count_k(const int* __restrict__ dstv, int E) {
    int i = blockIdx.x * blockDim.x + threadIdx.x;
    if (i < E) atomicAdd(&g_cnt[dstv[i]], 1);
}
__global__ void scan2_k(int N) {
    __shared__ int wsum[32];
    int tid = threadIdx.x;
    int lane = tid & 31, wid = tid >> 5;
    int per = (N + 1023) >> 10;
    int start = tid * per;
    int s = 0;
    for (int i = 0; i < per; ++i) {
        int idx = start + i;
        if (idx < N) s += g_cnt[idx];
    }
    int v = s;
    #pragma unroll
    for (int off = 1; off < 32; off <<= 1) {
        int t = __shfl_up_sync(0xffffffffu, v, off);
        if (lane >= off) v += t;
    }
    if (lane == 31) wsum[wid] = v;
    __syncthreads();
    if (wid == 0) {
        int w = wsum[lane];
        #pragma unroll
        for (int off = 1; off < 32; off <<= 1) {
            int t = __shfl_up_sync(0xffffffffu, w, off);
            if (lane >= off) w += t;
        }
        wsum[lane] = w;
    }
    __syncthreads();
    int excl = v - s + (wid ? wsum[wid - 1] : 0);
    int run = excl;
    for (int i = 0; i < per; ++i) {
        int idx = start + i;
        if (idx < N) {
            int c = g_cnt[idx];
            g_cur[idx] = run;
            run += c;
            g_rp[idx + 1] = run;
        }
    }
    if (tid == 0) g_rp[0] = 0;
}
__global__ void scatter_k(const int* __restrict__ srcv, const int* __restrict__ dstv,
                          int E, int N) {
    int i = blockIdx.x * blockDim.x + threadIdx.x;
    if (i < E) {
        int d = dstv[i];
        int pos = atomicAdd(&g_cur[d], 1);
        g_csrc[pos] = srcv[i];
    } else if (i < E + N) {
        int n = i - E;
        int pos = atomicAdd(&g_cur[n], 1);
        g_csrc[pos] = n;
    }
}

// ---------------- weights transpose + hi/lo + bias pack + cnt init, ONE launch ----------------
__device__ __forceinline__ uint32_t pack_bf2(__nv_bfloat16 a, __nv_bfloat16 b) {
    return (uint32_t)__bfloat16_as_ushort(a) | ((uint32_t)__bfloat16_as_ushort(b) << 16);
}

__global__ void conv_all_k(const float* __restrict__ w0, const float* __restrict__ w1,
                           const float* __restrict__ w2, const float* __restrict__ w3,
                           const float* __restrict__ w4, const float* __restrict__ w5,
                           const float* __restrict__ w6,
                           const float* __restrict__ b0, const float* __restrict__ b1,
                           const float* __restrict__ b2, const float* __restrict__ b3,
                           const float* __restrict__ b4, const float* __restrict__ b5,
                           const float* __restrict__ b6, int N) {
    int i = blockIdx.x * blockDim.x + threadIdx.x;
    if (i < N) g_cnt[i] = 1;   // self-loop pre-count
    const int WTH = 2048 + 6 * 8192;   // 51200
    if (i < WTH) {
        const float* W; int cols, rowoff, n, kg;
        if (i < 2048) { W = w0; cols = 128; rowoff = 0; n = i & 127; kg = i >> 7; }
        else {
            int j = i - 2048;
            int s = j >> 13;
            int r = j & 8191;
            n = r & 511; kg = r >> 9;
            W = (s == 0) ? w1 : (s == 1) ? w2 : (s == 2) ? w3 : (s == 3) ? w4 : (s == 4) ? w5 : w6;
            cols = 512; rowoff = 128 + s * 512;
        }
        int k0 = kg * 8;
        __nv_bfloat16 h8[8], l8v[8];
        #pragma unroll
        for (int q = 0; q < 8; ++q) {
            float v = W[(size_t)(k0 + q) * cols + n];
            __nv_bfloat16 h = __float2bfloat16(v);
            h8[q] = h;
            l8v[q] = __float2bfloat16(v - __bfloat162float(h));
        }
        uint4 hv, lv;
        hv.x = pack_bf2(h8[0], h8[1]); hv.y = pack_bf2(h8[2], h8[3]);
        hv.z = pack_bf2(h8[4], h8[5]); hv.w = pack_bf2(h8[6], h8[7]);
        lv.x = pack_bf2(l8v[0], l8v[1]); lv.y = pack_bf2(l8v[2], l8v[3]);
        lv.z = pack_bf2(l8v[4], l8v[5]); lv.w = pack_bf2(l8v[6], l8v[7]);
        *(uint4*)(g_wthi + (size_t)(rowoff + n) * 128 + k0) = hv;
        *(uint4*)(g_wtlo + (size_t)(rowoff + n) * 128 + k0) = lv;
    } else if (i < WTH + WT_ROWS) {
        int j = i - WTH;
        float v;
        if (j < 128) v = b0[j];
        else {
            int s = (j - 128) >> 9, t = (j - 128) & 511;
            const float* B = (s == 0) ? b1 : (s == 1) ? b2 : (s == 2) ? b3
                           : (s == 3) ? b4 : (s == 4) ? b5 : b6;
            v = B[t];
        }
        g_biasc[j] = v;
    }
}

// ---------------- activation fp32 -> bf16 hi/lo (x only) ----------------
__global__ void conv_a_k(const float* __restrict__ src, int n4) {
    int i = blockIdx.x * blockDim.x + threadIdx.x;
    if (i < n4) {
        float4 v = ((const float4*)src)[i];
        __nv_bfloat16 hx = __float2bfloat16(v.x);
        __nv_bfloat16 hy = __float2bfloat16(v.y);
        __nv_bfloat16 hz = __float2bfloat16(v.z);
        __nv_bfloat16 hw = __float2bfloat16(v.w);
        __nv_bfloat16 lx = __float2bfloat16(v.x - __bfloat162float(hx));
        __nv_bfloat16 ly = __float2bfloat16(v.y - __bfloat162float(hy));
        __nv_bfloat16 lz = __float2bfloat16(v.z - __bfloat162float(hz));
        __nv_bfloat16 lw = __float2bfloat16(v.w - __bfloat162float(hw));
        ((uint2*)g_ahi)[i] = make_uint2(pack_bf2(hx, hy), pack_bf2(hz, hw));
        ((uint2*)g_alo)[i] = make_uint2(pack_bf2(lx, ly), pack_bf2(lz, lw));
    }
}

// ======== bf16x3 GEMM v4: persistent col tile, double-buffered A, 512 threads ========
#define TSTRIDE 272
#define TILE_B (128 * TSTRIDE)
#define GMM_SMEM (6 * TILE_B)

__device__ __forceinline__ uint32_t smem_u32(const void* p) {
    uint32_t a;
    asm("{ .reg .u64 t; cvta.to.shared.u64 t, %1; cvt.u32.u64 %0, t; }" : "=r"(a) : "l"(p));
    return a;
}

#define CP16(dst, src, sz) \
    asm volatile("cp.async.cg.shared.global [%0], [%1], 16, %2;" \
                 :: "r"(dst), "l"(src), "r"(sz) : "memory")
#define CP_COMMIT() asm volatile("cp.async.commit_group;" ::: "memory")
#define CP_WAIT0()  asm volatile("cp.async.wait_group 0;" ::: "memory")
#define CP_WAIT1()  asm volatile("cp.async.wait_group 1;" ::: "memory")

#define LDMX4(r0, r1, r2, r3, addr) \
    asm volatile("ldmatrix.sync.aligned.m8n8.x4.shared.b16 {%0,%1,%2,%3}, [%4];" \
                 : "=r"(r0), "=r"(r1), "=r"(r2), "=r"(r3) : "r"(addr))

#define MMA_BF16(c, a0, a1, a2, a3, b0, b1) \
    asm volatile("mma.sync.aligned.m16n8k16.row.col.f32.bf16.bf16.f32 " \
                 "{%0,%1,%2,%3}, {%4,%5,%6,%7}, {%8,%9}, {%0,%1,%2,%3};" \
                 : "+f"((c)[0]), "+f"((c)[1]), "+f"((c)[2]), "+f"((c)[3]) \
                 : "r"(a0), "r"(a1), "r"(a2), "r"(a3), "r"(b0), "r"(b1))

__device__ __forceinline__ void prefetch_A(uint32_t uAhi, uint32_t uAlo,
                                           const __nv_bfloat16* Ahi, const __nv_bfloat16* Alo,
                                           int row0, int M, int tid) {
    #pragma unroll
    for (int it = 0; it < 4; ++it) {
        int idx = it * 512 + tid;
        int row = idx >> 4, c = idx & 15;
        int grow = row0 + row;
        int ok = grow < M;
        int srow = ok ? grow : 0;
        uint32_t sz = ok ? 16u : 0u;
        CP16(uAhi + row * TSTRIDE + c * 16,
             (const char*)(Ahi + (size_t)srow * 128) + c * 16, sz);
        CP16(uAlo + row * TSTRIDE + c * 16,
             (const char*)(Alo + (size_t)srow * 128) + c * 16, sz);
    }
}

__global__ void __launch_bounds__(512, 1)
gemm_mma_k(const __nv_bfloat16* __restrict__ Ahi, const __nv_bfloat16* __restrict__ Alo, int M,
           const __nv_bfloat16* __restrict__ Bhi, const __nv_bfloat16* __restrict__ Blo,
           const float* __restrict__ bias,
           float* __restrict__ out, float* __restrict__ out2, int split,
           int ldo, int do_relu, int conv_out) {
    extern __shared__ char sm[];
    char* sBhi = sm;
    char* sBlo = sm + TILE_B;
    char* sA[2][2];
    sA[0][0] = sm + 2 * TILE_B;
    sA[0][1] = sm + 3 * TILE_B;
    sA[1][0] = sm + 4 * TILE_B;
    sA[1][1] = sm + 5 * TILE_B;

    int tid = threadIdx.x;
    int wc0 = blockIdx.y * 128;
    int oc  = wc0;
    if (oc >= split) { out = out2; oc -= split; }

    uint32_t uBhi = smem_u32(sBhi), uBlo = smem_u32(sBlo);
    uint32_t uA[2][2];
    #pragma unroll
    for (int s = 0; s < 2; ++s) { uA[s][0] = smem_u32(sA[s][0]); uA[s][1] = smem_u32(sA[s][1]); }

    #pragma unroll
    for (int it = 0; it < 4; ++it) {
        int idx = it * 512 + tid;
        int row = idx >> 4, c = idx & 15;
        CP16(uBhi + row * TSTRIDE + c * 16,
             (const char*)(Bhi + (size_t)(wc0 + row) * 128) + c * 16, 16u);
        CP16(uBlo + row * TSTRIDE + c * 16,
             (const char*)(Blo + (size_t)(wc0 + row) * 128) + c * 16, 16u);
    }
    int nrt = (M + 127) >> 7;
    int stride = gridDim.x;
    int r0 = blockIdx.x;
    if (r0 < nrt)
        prefetch_A(uA[0][0], uA[0][1], Ahi, Alo, r0 * 128, M, tid);
    CP_COMMIT();

    int wid = tid >> 5;
    int lane = tid & 31;
    int m0 = (wid & 3) * 32;
    int n0 = (wid >> 2) * 32;

    int gq = lane >> 3, l8 = lane & 7;
    int fr_row = (gq & 1) * 8 + l8;
    int fr_col = (gq >> 1) * 16;

    uint32_t aoff[2], boff[2];
    #pragma unroll
    for (int mt = 0; mt < 2; ++mt)
        aoff[mt] = (uint32_t)((m0 + mt * 16 + fr_row) * TSTRIDE + fr_col);
    #pragma unroll
    for (int nt2 = 0; nt2 < 2; ++nt2)
        boff[nt2] = (uint32_t)((n0 + nt2 * 16 + fr_row) * TSTRIDE + fr_col);

    int qr = lane >> 2;
    int qc = (lane & 3) * 2;
    float2 bv[4];
    #pragma unroll
    for (int nt = 0; nt < 4; ++nt)
        bv[nt] = *(const float2*)(bias + wc0 + n0 + nt * 8 + qc);

    int buf = 0;
    for (int r = r0; r < nrt; r += stride) {
        int rn = r + stride;
        if (rn < nrt)
            prefetch_A(uA[buf ^ 1][0], uA[buf ^ 1][1], Ahi, Alo, rn * 128, M, tid);
        CP_COMMIT();
        if (rn < nrt) CP_WAIT1(); else CP_WAIT0();
        __syncthreads();

        uint32_t uAhi = uA[buf][0], uAlo = uA[buf][1];

        float c[2][4][4];
        #pragma unroll
        for (int mt = 0; mt < 2; ++mt)
            #pragma unroll
            for (int nt = 0; nt < 4; ++nt)
                #pragma unroll
                for (int q = 0; q < 4; ++q) c[mt][nt][q] = 0.f;

        #pragma unroll
        for (int kk = 0; kk < 8; ++kk) {
            uint32_t ah[2][4], al2[2][4];
            #pragma unroll
            for (int mt = 0; mt < 2; ++mt) {
                LDMX4(ah[mt][0], ah[mt][1], ah[mt][2], ah[mt][3], uAhi + aoff[mt] + kk * 32);
                LDMX4(al2[mt][0], al2[mt][1], al2[mt][2], al2[mt][3], uAlo + aoff[mt] + kk * 32);
            }
            uint32_t bh[2][4], bl[2][4];
            #pragma unroll
            for (int nt2 = 0; nt2 < 2; ++nt2) {
                LDMX4(bh[nt2][0], bh[nt2][1], bh[nt2][2], bh[nt2][3], uBhi + boff[nt2] + kk * 32);
                LDMX4(bl[nt2][0], bl[nt2][1], bl[nt2][2], bl[nt2][3], uBlo + boff[nt2] + kk * 32);
            }
            #pragma unroll
            for (int mt = 0; mt < 2; ++mt)
                #pragma unroll
                for (int nt = 0; nt < 4; ++nt) {
                    int nt2 = nt >> 1, odd = nt & 1;
                    MMA_BF16(c[mt][nt], ah[mt][0], ah[mt][1], ah[mt][2], ah[mt][3],
                             bh[nt2][odd], bh[nt2][2 + odd]);
                    MMA_BF16(c[mt][nt], ah[mt][0], ah[mt][1], ah[mt][2], ah[mt][3],
                             bl[nt2][odd], bl[nt2][2 + odd]);
                    MMA_BF16(c[mt][nt], al2[mt][0], al2[mt][1], al2[mt][2], al2[mt][3],
                             bh[nt2][odd], bh[nt2][2 + odd]);
                }
        }

        int row0 = r * 128;
        #pragma unroll
        for (int mt = 0; mt < 2; ++mt) {
            int r_lo = row0 + m0 + mt * 16 + qr;
            #pragma unroll
            for (int nt = 0; nt < 4; ++nt) {
                int colb = n0 + nt * 8 + qc;
                float2 v0 = make_float2(c[mt][nt][0] + bv[nt].x, c[mt][nt][1] + bv[nt].y);
                float2 v1 = make_float2(c[mt][nt][2] + bv[nt].x, c[mt][nt][3] + bv[nt].y);
                if (do_relu) {
                    v0.x = fmaxf(v0.x, 0.f); v0.y = fmaxf(v0.y, 0.f);
                    v1.x = fmaxf(v1.x, 0.f); v1.y = fmaxf(v1.y, 0.f);
                }
                #pragma unroll
                for (int half = 0; half < 2; ++half) {
                    int rr = r_lo + half * 8;
                    float2 vv = half ? v1 : v0;
                    if (rr < M) {
                        *(float2*)(out + (size_t)rr * ldo + oc + colb) = vv;
                        if (conv_out) {
                            __nv_bfloat16 hx = __float2bfloat16(vv.x);
                            __nv_bfloat16 hy = __float2bfloat16(vv.y);
                            __nv_bfloat16 lx = __float2bfloat16(vv.x - __bfloat162float(hx));
                            __nv_bfloat16 ly = __float2bfloat16(vv.y - __bfloat162float(hy));
                            size_t ai = (size_t)rr * 128 + oc + colb;
                            *(uint32_t*)(g_ahi + ai) = pack_bf2(hx, hy);
                            *(uint32_t*)(g_alo + ai) = pack_bf2(lx, ly);
                        }
                    }
                }
            }
        }
        __syncthreads();
        buf ^= 1;
    }
}

// ===== GATv2 (R10 math), ONE warp per block: zero intra-block imbalance =====
#define LRD(t, x4, r4, a4) do {                                        \
    float ex = (x4).x + (r4).x; ex = fmaxf(ex, 0.2f * ex); t = fmaf(ex, (a4).x, t); \
    float ey = (x4).y + (r4).y; ey = fmaxf(ey, 0.2f * ey); t = fmaf(ey, (a4).y, t); \
    float ez = (x4).z + (r4).z; ez = fmaxf(ez, 0.2f * ez); t = fmaf(ez, (a4).z, t); \
    float ew = (x4).w + (r4).w; ew = fmaxf(ew, 0.2f * ew); t = fmaf(ew, (a4).w, t); \
} while (0)

template <int WRITE_H>
__global__ void __launch_bounds__(32)
gat2_k(const float* __restrict__ xlxr,
       const float* __restrict__ hres,
       const float* __restrict__ att,
       const float* __restrict__ gatb,
       const float* __restrict__ lng,
       const float* __restrict__ lnb,
       const float* __restrict__ headW,
       const float* __restrict__ headb,
       float* __restrict__ outh,
       float* __restrict__ outsc,
       int N) {
    int n    = blockIdx.x;
    int lane = threadIdx.x;
    if (n >= N) return;
    int g  = lane >> 3;
    int l8 = lane & 7;
    int cb = g * 32 + l8 * 4;

    float4 atv[4], xrv[4];
    const float4* ap = (const float4*)att + cb;
    const float4* xp = (const float4*)(xlxr + (size_t)n * 1024 + 512) + cb;
    #pragma unroll
    for (int j = 0; j < 4; ++j) { atv[j] = ap[j]; xrv[j] = xp[j]; }

    float m = -CUDART_INF_F, d = 0.f;
    float4 acc[4];
    #pragma unroll
    for (int j = 0; j < 4; ++j) acc[j] = make_float4(0.f, 0.f, 0.f, 0.f);

    int e = g_rp[n], end = g_rp[n + 1];
    for (; e + 2 <= end; e += 2) {
        int s0 = g_csrc[e];
        int s1 = g_csrc[e + 1];
        const float4* q0 = (const float4*)(xlxr + (size_t)s0 * 1024) + cb;
        const float4* q1 = (const float4*)(xlxr + (size_t)s1 * 1024) + cb;
        float4 x0[4], x1[4];
        #pragma unroll
        for (int j = 0; j < 4; ++j) x0[j] = q0[j];
        #pragma unroll
        for (int j = 0; j < 4; ++j) x1[j] = q1[j];

        float t0 = 0.f, t1 = 0.f;
        #pragma unroll
        for (int j = 0; j < 4; ++j) { LRD(t0, x0[j], xrv[j], atv[j]); LRD(t1, x1[j], xrv[j], atv[j]); }
        t0 += __shfl_xor_sync(0xffffffffu, t0, 1);
        t1 += __shfl_xor_sync(0xffffffffu, t1, 1);
        t0 += __shfl_xor_sync(0xffffffffu, t0, 2);
        t1 += __shfl_xor_sync(0xffffffffu, t1, 2);
        t0 += __shfl_xor_sync(0xffffffffu, t0, 4);
        t1 += __shfl_xor_sync(0xffffffffu, t1, 4);

        float mn = fmaxf(m, fmaxf(t0, t1));
        float sc = __expf(m - mn);
        float p0 = __expf(t0 - mn);
        float p1 = __expf(t1 - mn);
        d = fmaf(d, sc, p0 + p1);
        #pragma unroll
        for (int j = 0; j < 4; ++j) {
            acc[j].x = fmaf(acc[j].x, sc, fmaf(p0, x0[j].x, p1 * x1[j].x));
            acc[j].y = fmaf(acc[j].y, sc, fmaf(p0, x0[j].y, p1 * x1[j].y));
            acc[j].z = fmaf(acc[j].z, sc, fmaf(p0, x0[j].z, p1 * x1[j].z));
            acc[j].w = fmaf(acc[j].w, sc, fmaf(p0, x0[j].w, p1 * x1[j].w));
        }
        m = mn;
    }
    if (e < end) {
        int s0 = g_csrc[e];
        const float4* q0 = (const float4*)(xlxr + (size_t)s0 * 1024) + cb;
        float4 x0[4];
        #pragma unroll
        for (int j = 0; j < 4; ++j) x0[j] = q0[j];
        float t0 = 0.f;
        #pragma unroll
        for (int j = 0; j < 4; ++j) LRD(t0, x0[j], xrv[j], atv[j]);
        t0 += __shfl_xor_sync(0xffffffffu, t0, 1);
        t0 += __shfl_xor_sync(0xffffffffu, t0, 2);
        t0 += __shfl_xor_sync(0xffffffffu, t0, 4);
        float mn = fmaxf(m, t0);
        float sc = __expf(m - mn);
        float p0 = __expf(t0 - mn);
        d = fmaf(d, sc, p0);
        #pragma unroll
        for (int j = 0; j < 4; ++j) {
            acc[j].x = fmaf(acc[j].x, sc, p0 * x0[j].x);
            acc[j].y = fmaf(acc[j].y, sc, p0 * x0[j].y);
            acc[j].z = fmaf(acc[j].z, sc, p0 * x0[j].z);
            acc[j].w = fmaf(acc[j].w, sc, p0 * x0[j].w);
        }
        m = mn;
    }

    float inv = 0.25f / d;
    float* a = (float*)acc;
    #pragma unroll
    for (int i = 0; i < 16; ++i) {
        float v = a[i] * inv;
        v += __shfl_xor_sync(0xffffffffu, v, 8);
        v += __shfl_xor_sync(0xffffffffu, v, 16);
        a[i] = v;
    }

    int fb = l8 * 4;
    const float4* gbp = (const float4*)gatb + fb;
    const float4* hrp = (const float4*)(hres + (size_t)n * 128) + fb;
    float4 v4[4];
    float s1 = 0.f, s2 = 0.f;
    #pragma unroll
    for (int j = 0; j < 4; ++j) {
        float4 gb = gbp[j], hr = hrp[j];
        v4[j].x = acc[j].x + gb.x + hr.x;
        v4[j].y = acc[j].y + gb.y + hr.y;
        v4[j].z = acc[j].z + gb.z + hr.z;
        v4[j].w = acc[j].w + gb.w + hr.w;
        s1 += v4[j].x + v4[j].y + v4[j].z + v4[j].w;
        s2 += v4[j].x * v4[j].x + v4[j].y * v4[j].y + v4[j].z * v4[j].z + v4[j].w * v4[j].w;
    }
    s1 += __shfl_xor_sync(0xffffffffu, s1, 1);
    s2 += __shfl_xor_sync(0xffffffffu, s2, 1);
    s1 += __shfl_xor_sync(0xffffffffu, s1, 2);
    s2 += __shfl_xor_sync(0xffffffffu, s2, 2);
    s1 += __shfl_xor_sync(0xffffffffu, s1, 4);
    s2 += __shfl_xor_sync(0xffffffffu, s2, 4);
    float mean = s1 * (1.f / 128.f);
    float var  = s2 * (1.f / 128.f) - mean * mean;
    float rstd = rsqrtf(var + 1e-5f);

    const float4* gp = (const float4*)lng + fb;
    const float4* bp = (const float4*)lnb + fb;
    float4 y4[4];
    #pragma unroll
    for (int j = 0; j < 4; ++j) {
        float4 gg = gp[j], bb = bp[j];
        y4[j].x = fmaxf((v4[j].x - mean) * rstd * gg.x + bb.x, 0.f);
        y4[j].y = fmaxf((v4[j].y - mean) * rstd * gg.y + bb.y, 0.f);
        y4[j].z = fmaxf((v4[j].z - mean) * rstd * gg.z + bb.z, 0.f);
        y4[j].w = fmaxf((v4[j].w - mean) * rstd * gg.w + bb.w, 0.f);
    }

    if (WRITE_H) {
        if (g == 0) {
            float4* op = (float4*)outh + (size_t)n * 32 + fb;
            #pragma unroll
            for (int j = 0; j < 4; ++j) {
                op[j] = y4[j];
                __nv_bfloat16 hx = __float2bfloat16(y4[j].x);
                __nv_bfloat16 hy = __float2bfloat16(y4[j].y);
                __nv_bfloat16 hz = __float2bfloat16(y4[j].z);
                __nv_bfloat16 hw = __float2bfloat16(y4[j].w);
                __nv_bfloat16 lx = __float2bfloat16(y4[j].x - __bfloat162float(hx));
                __nv_bfloat16 ly = __float2bfloat16(y4[j].y - __bfloat162float(hy));
                __nv_bfloat16 lz = __float2bfloat16(y4[j].z - __bfloat162float(hz));
                __nv_bfloat16 lw = __float2bfloat16(y4[j].w - __bfloat162float(hw));
                size_t ai = (size_t)n * 32 + fb + j;
                ((uint2*)g_ahi)[ai] = make_uint2(pack_bf2(hx, hy), pack_bf2(hz, hw));
                ((uint2*)g_alo)[ai] = make_uint2(pack_bf2(lx, ly), pack_bf2(lz, lw));
            }
        }
    } else {
        const float4* wp = (const float4*)headW + fb;
        float pp = 0.f;
        #pragma unroll
        for (int j = 0; j < 4; ++j) {
            float4 w4 = wp[j];
            pp = fmaf(y4[j].x, w4.x, pp);
            pp = fmaf(y4[j].y, w4.y, pp);
            pp = fmaf(y4[j].z, w4.z, pp);
            pp = fmaf(y4[j].w, w4.w, pp);
        }
        pp += __shfl_xor_sync(0xffffffffu, pp, 1);
        pp += __shfl_xor_sync(0xffffffffu, pp, 2);
        pp += __shfl_xor_sync(0xffffffffu, pp, 4);
        if (lane == 0) outsc[n] = pp + headb[0];
    }
}

// ---------------- launch ----------------
extern "C" void kernel_launch(void* const* d_in, const int* in_sizes, int n_in,
                              void* d_out, int out_size) {
    const float* x     = (const float*)d_in[0];
    const int*   ei    = (const int*)d_in[1];
    const float* W_in  = (const float*)d_in[2];
    const float* b_in  = (const float*)d_in[3];
    const float* c1_Wl = (const float*)d_in[4];
    const float* c1_bl = (const float*)d_in[5];
    const float* c1_Wr = (const float*)d_in[6];
    const float* c1_br = (const float*)d_in[7];
    const float* c1_att= (const float*)d_in[8];
    const float* c1_b  = (const float*)d_in[9];
    const float* ln1_g = (const float*)d_in[10];
    const float* ln1_b = (const float*)d_in[11];
    const float* a_Wl  = (const float*)d_in[12];
    const float* a_bl  = (const float*)d_in[13];
    const float* a_Wr  = (const float*)d_in[14];
    const float* a_br  = (const float*)d_in[15];
    const float* a_att = (const float*)d_in[16];
    const float* a_b   = (const float*)d_in[17];
    const float* aln_g = (const float*)d_in[18];
    const float* aln_b = (const float*)d_in[19];
    const float* ah_W  = (const float*)d_in[20];
    const float* ah_b  = (const float*)d_in[21];
    const float* k_Wl  = (const float*)d_in[22];
    const float* k_bl  = (const float*)d_in[23];
    const float* k_Wr  = (const float*)d_in[24];
    const float* k_br  = (const float*)d_in[25];
    const float* k_att = (const float*)d_in[26];
    const float* k_b   = (const float*)d_in[27];
    const float* kln_g = (const float*)d_in[28];
    const float* kln_b = (const float*)d_in[29];
    const float* kh_W  = (const float*)d_in[30];
    const float* kh_b  = (const float*)d_in[31];

    int N = in_sizes[0] / 128;
    int E = in_sizes[1] / 2;
    float* out = (float*)d_out;

    float *h1, *h2, *xlxr, *xlxr2, *biasc;
    __nv_bfloat16 *ahi, *alo, *wthi, *wtlo;
    cudaGetSymbolAddress((void**)&h1, g_h1);
    cudaGetSymbolAddress((void**)&h2, g_h2);
    cudaGetSymbolAddress((void**)&xlxr, g_xlxr);
    cudaGetSymbolAddress((void**)&xlxr2, g_xlxr2);
    cudaGetSymbolAddress((void**)&biasc, g_biasc);
    cudaGetSymbolAddress((void**)&ahi, g_ahi);
    cudaGetSymbolAddress((void**)&alo, g_alo);
    cudaGetSymbolAddress((void**)&wthi, g_wthi);
    cudaGetSymbolAddress((void**)&wtlo, g_wtlo);

    cudaFuncSetAttribute(gemm_mma_k, cudaFuncAttributeMaxDynamicSharedMemorySize, GMM_SMEM);

    int gc = (N * 32 + 255) / 256;
    const int NOSPLIT = 1 << 30;

    conv_all_k<<<(2048 + 6 * 8192 + WT_ROWS + 255) / 256, 256>>>(          // 1
        W_in, c1_Wl, c1_Wr, a_Wl, a_Wr, k_Wl, k_Wr,
        b_in, c1_bl, c1_br, a_bl, a_br, k_bl, k_br, N);
    conv_a_k<<<gc, 256>>>(x, N * 32);                                      // 2
    gemm_mma_k<<<dim3(148, 1), 512, GMM_SMEM>>>(ahi, alo, N,               // 3: input layer
        wthi, wtlo, biasc, h1, (float*)0, NOSPLIT, 128, 1, 1);
    gemm_mma_k<<<dim3(18, 8), 512, GMM_SMEM>>>(ahi, alo, N,                // 4 <- profiled
        wthi + (size_t)128 * 128, wtlo + (size_t)128 * 128, biasc + 128,
        xlxr, (float*)0, NOSPLIT, 1024, 0, 0);

    count_k<<<(E + 255) / 256, 256>>>(ei + E, E);                          // 5
    scan2_k<<<1, 1024>>>(N);                                               // 6
    scatter_k<<<(E + N + 255) / 256, 256>>>(ei, ei + E, E, N);             // 7

    gat2_k<1><<<N, 32>>>(xlxr, h1, c1_att, c1_b, ln1_g, ln1_b,             // 8
                         (const float*)0, (const float*)0, h2, (float*)0, N);

    gemm_mma_k<<<dim3(9, 16), 512, GMM_SMEM>>>(ahi, alo, N,                // 9
        wthi + (size_t)1152 * 128, wtlo + (size_t)1152 * 128, biasc + 1152,
        xlxr, xlxr2, 1024, 1024, 0, 0);

    gat2_k<0><<<N, 32>>>(xlxr, h2, a_att, a_b, aln_g, aln_b,               // 10
                         ah_W, ah_b, (float*)0, out, N);
    gat2_k<0><<<N, 32>>>(xlxr2, h2, k_att, k_b, kln_g, kln_b,              // 11
                         kh_W, kh_b, (float*)0, out + N, N);
}

// round 14
// speedup vs baseline: 1.0798x; 1.0017x over previous
#include <cuda_runtime.h>
#include <cuda_bf16.h>
#include <math_constants.h>
#include <cstdint>

// Problem constants (fixed dataset shapes)
#define NMAX 20000
#define EMAX 320000
#define ETOT (EMAX + NMAX)

// ---------------- device scratch (static allocations only) ----------------
__device__ float g_h1[(size_t)NMAX * 128];
__device__ float g_h2[(size_t)NMAX * 128];
__device__ float g_xlxr[(size_t)NMAX * 1024];    // layer1 & actor: [xl(512) | xr(512)]
__device__ float g_xlxr2[(size_t)NMAX * 1024];   // critic
__device__ int   g_cnt[NMAX];
__device__ int   g_rp[NMAX + 1];
__device__ int   g_cur[NMAX];
__device__ int   g_csrc[ETOT];

// bf16 hi/lo activations
__device__ __nv_bfloat16 g_ahi[(size_t)NMAX * 128];
__device__ __nv_bfloat16 g_alo[(size_t)NMAX * 128];
// transposed bf16 hi/lo weights: rows = 128(W_in) + 6*512 = 3200, each row 128 bf16
#define WT_ROWS 3200
__device__ __nv_bfloat16 g_wthi[(size_t)WT_ROWS * 128];
__device__ __nv_bfloat16 g_wtlo[(size_t)WT_ROWS * 128];
// packed biases, index-matched to wt rows
__device__ float g_biasc[WT_ROWS];

// ---------------- CSR build ----------------
__global__ void count_k(const int* __restrict__ dstv, int E) {
    int i = blockIdx.x * blockDim.x + threadIdx.x;
    if (i < E) atomicAdd(&g_cnt[dstv[i]], 1);
}
__global__ void scan2_k(int N) {
    __shared__ int wsum[32];
    int tid = threadIdx.x;
    int lane = tid & 31, wid = tid >> 5;
    int per = (N + 1023) >> 10;
    int start = tid * per;
    int s = 0;
    for (int i = 0; i < per; ++i) {
        int idx = start + i;
        if (idx < N) s += g_cnt[idx];
    }
    int v = s;
    #pragma unroll
    for (int off = 1; off < 32; off <<= 1) {
        int t = __shfl_up_sync(0xffffffffu, v, off);
        if (lane >= off) v += t;
    }
    if (lane == 31) wsum[wid] = v;
    __syncthreads();
    if (wid == 0) {
        int w = wsum[lane];
        #pragma unroll
        for (int off = 1; off < 32; off <<= 1) {
            int t = __shfl_up_sync(0xffffffffu, w, off);
            if (lane >= off) w += t;
        }
        wsum[lane] = w;
    }
    __syncthreads();
    int excl = v - s + (wid ? wsum[wid - 1] : 0);
    int run = excl;
    for (int i = 0; i < per; ++i) {
        int idx = start + i;
        if (idx < N) {
            int c = g_cnt[idx];
            g_cur[idx] = run;
            run += c;
            g_rp[idx + 1] = run;
        }
    }
    if (tid == 0) g_rp[0] = 0;
}
__global__ void scatter_k(const int* __restrict__ srcv, const int* __restrict__ dstv,
                          int E, int N) {
    int i = blockIdx.x * blockDim.x + threadIdx.x;
    if (i < E) {
        int d = dstv[i];
        int pos = atomicAdd(&g_cur[d], 1);
        g_csrc[pos] = srcv[i];
    } else if (i < E + N) {
        int n = i - E;
        int pos = atomicAdd(&g_cur[n], 1);
        g_csrc[pos] = n;
    }
}

// ---------------- weights transpose + hi/lo + bias pack + cnt init, ONE launch ----------------
__device__ __forceinline__ uint32_t pack_bf2(__nv_bfloat16 a, __nv_bfloat16 b) {
    return (uint32_t)__bfloat16_as_ushort(a) | ((uint32_t)__bfloat16_as_ushort(b) << 16);
}

__global__ void conv_all_k(const float* __restrict__ w0, const float* __restrict__ w1,
                           const float* __restrict__ w2, const float* __restrict__ w3,
                           const float* __restrict__ w4, const float* __restrict__ w5,
                           const float* __restrict__ w6,
                           const float* __restrict__ b0, const float* __restrict__ b1,
                           const float* __restrict__ b2, const float* __restrict__ b3,
                           const float* __restrict__ b4, const float* __restrict__ b5,
                           const float* __restrict__ b6, int N) {
    int i = blockIdx.x * blockDim.x + threadIdx.x;
    if (i < N) g_cnt[i] = 1;   // self-loop pre-count
    const int WTH = 2048 + 6 * 8192;   // 51200
    if (i < WTH) {
        const float* W; int cols, rowoff, n, kg;
        if (i < 2048) { W = w0; cols = 128; rowoff = 0; n = i & 127; kg = i >> 7; }
        else {
            int j = i - 2048;
            int s = j >> 13;
            int r = j & 8191;
            n = r & 511; kg = r >> 9;
            W = (s == 0) ? w1 : (s == 1) ? w2 : (s == 2) ? w3 : (s == 3) ? w4 : (s == 4) ? w5 : w6;
            cols = 512; rowoff = 128 + s * 512;
        }
        int k0 = kg * 8;
        __nv_bfloat16 h8[8], l8v[8];
        #pragma unroll
        for (int q = 0; q < 8; ++q) {
            float v = W[(size_t)(k0 + q) * cols + n];
            __nv_bfloat16 h = __float2bfloat16(v);
            h8[q] = h;
            l8v[q] = __float2bfloat16(v - __bfloat162float(h));
        }
        uint4 hv, lv;
        hv.x = pack_bf2(h8[0], h8[1]); hv.y = pack_bf2(h8[2], h8[3]);
        hv.z = pack_bf2(h8[4], h8[5]); hv.w = pack_bf2(h8[6], h8[7]);
        lv.x = pack_bf2(l8v[0], l8v[1]); lv.y = pack_bf2(l8v[2], l8v[3]);
        lv.z = pack_bf2(l8v[4], l8v[5]); lv.w = pack_bf2(l8v[6], l8v[7]);
        *(uint4*)(g_wthi + (size_t)(rowoff + n) * 128 + k0) = hv;
        *(uint4*)(g_wtlo + (size_t)(rowoff + n) * 128 + k0) = lv;
    } else if (i < WTH + WT_ROWS) {
        int j = i - WTH;
        float v;
        if (j < 128) v = b0[j];
        else {
            int s = (j - 128) >> 9, t = (j - 128) & 511;
            const float* B = (s == 0) ? b1 : (s == 1) ? b2 : (s == 2) ? b3
                           : (s == 3) ? b4 : (s == 4) ? b5 : b6;
            v = B[t];
        }
        g_biasc[j] = v;
    }
}

// ---------------- activation fp32 -> bf16 hi/lo (x only) ----------------
__global__ void conv_a_k(const float* __restrict__ src, int n4) {
    int i = blockIdx.x * blockDim.x + threadIdx.x;
    if (i < n4) {
        float4 v = ((const float4*)src)[i];
        __nv_bfloat16 hx = __float2bfloat16(v.x);
        __nv_bfloat16 hy = __float2bfloat16(v.y);
        __nv_bfloat16 hz = __float2bfloat16(v.z);
        __nv_bfloat16 hw = __float2bfloat16(v.w);
        __nv_bfloat16 lx = __float2bfloat16(v.x - __bfloat162float(hx));
        __nv_bfloat16 ly = __float2bfloat16(v.y - __bfloat162float(hy));
        __nv_bfloat16 lz = __float2bfloat16(v.z - __bfloat162float(hz));
        __nv_bfloat16 lw = __float2bfloat16(v.w - __bfloat162float(hw));
        ((uint2*)g_ahi)[i] = make_uint2(pack_bf2(hx, hy), pack_bf2(hz, hw));
        ((uint2*)g_alo)[i] = make_uint2(pack_bf2(lx, ly), pack_bf2(lz, lw));
    }
}

// ======== bf16x3 GEMM v4: persistent col tile, double-buffered A, 512 threads ========
#define TSTRIDE 272
#define TILE_B (128 * TSTRIDE)
#define GMM_SMEM (6 * TILE_B)

__device__ __forceinline__ uint32_t smem_u32(const void* p) {
    uint32_t a;
    asm("{ .reg .u64 t; cvta.to.shared.u64 t, %1; cvt.u32.u64 %0, t; }" : "=r"(a) : "l"(p));
    return a;
}

#define CP16(dst, src, sz) \
    asm volatile("cp.async.cg.shared.global [%0], [%1], 16, %2;" \
                 :: "r"(dst), "l"(src), "r"(sz) : "memory")
#define CP_COMMIT() asm volatile("cp.async.commit_group;" ::: "memory")
#define CP_WAIT0()  asm volatile("cp.async.wait_group 0;" ::: "memory")
#define CP_WAIT1()  asm volatile("cp.async.wait_group 1;" ::: "memory")

#define LDMX4(r0, r1, r2, r3, addr) \
    asm volatile("ldmatrix.sync.aligned.m8n8.x4.shared.b16 {%0,%1,%2,%3}, [%4];" \
                 : "=r"(r0), "=r"(r1), "=r"(r2), "=r"(r3) : "r"(addr))

#define MMA_BF16(c, a0, a1, a2, a3, b0, b1) \
    asm volatile("mma.sync.aligned.m16n8k16.row.col.f32.bf16.bf16.f32 " \
                 "{%0,%1,%2,%3}, {%4,%5,%6,%7}, {%8,%9}, {%0,%1,%2,%3};" \
                 : "+f"((c)[0]), "+f"((c)[1]), "+f"((c)[2]), "+f"((c)[3]) \
                 : "r"(a0), "r"(a1), "r"(a2), "r"(a3), "r"(b0), "r"(b1))

__device__ __forceinline__ void prefetch_A(uint32_t uAhi, uint32_t uAlo,
                                           const __nv_bfloat16* Ahi, const __nv_bfloat16* Alo,
                                           int row0, int M, int tid) {
    #pragma unroll
    for (int it = 0; it < 4; ++it) {
        int idx = it * 512 + tid;
        int row = idx >> 4, c = idx & 15;
        int grow = row0 + row;
        int ok = grow < M;
        int srow = ok ? grow : 0;
        uint32_t sz = ok ? 16u : 0u;
        CP16(uAhi + row * TSTRIDE + c * 16,
             (const char*)(Ahi + (size_t)srow * 128) + c * 16, sz);
        CP16(uAlo + row * TSTRIDE + c * 16,
             (const char*)(Alo + (size_t)srow * 128) + c * 16, sz);
    }
}

__global__ void __launch_bounds__(512, 1)
gemm_mma_k(const __nv_bfloat16* __restrict__ Ahi, const __nv_bfloat16* __restrict__ Alo, int M,
           const __nv_bfloat16* __restrict__ Bhi, const __nv_bfloat16* __restrict__ Blo,
           const float* __restrict__ bias,
           float* __restrict__ out, float* __restrict__ out2, int split,
           int ldo, int do_relu, int conv_out) {
    extern __shared__ char sm[];
    char* sBhi = sm;
    char* sBlo = sm + TILE_B;
    char* sA[2][2];
    sA[0][0] = sm + 2 * TILE_B;
    sA[0][1] = sm + 3 * TILE_B;
    sA[1][0] = sm + 4 * TILE_B;
    sA[1][1] = sm + 5 * TILE_B;

    int tid = threadIdx.x;
    int wc0 = blockIdx.y * 128;
    int oc  = wc0;
    if (oc >= split) { out = out2; oc -= split; }

    uint32_t uBhi = smem_u32(sBhi), uBlo = smem_u32(sBlo);
    uint32_t uA[2][2];
    #pragma unroll
    for (int s = 0; s < 2; ++s) { uA[s][0] = smem_u32(sA[s][0]); uA[s][1] = smem_u32(sA[s][1]); }

    #pragma unroll
    for (int it = 0; it < 4; ++it) {
        int idx = it * 512 + tid;
        int row = idx >> 4, c = idx & 15;
        CP16(uBhi + row * TSTRIDE + c * 16,
             (const char*)(Bhi + (size_t)(wc0 + row) * 128) + c * 16, 16u);
        CP16(uBlo + row * TSTRIDE + c * 16,
             (const char*)(Blo + (size_t)(wc0 + row) * 128) + c * 16, 16u);
    }
    int nrt = (M + 127) >> 7;
    int stride = gridDim.x;
    int r0 = blockIdx.x;
    if (r0 < nrt)
        prefetch_A(uA[0][0], uA[0][1], Ahi, Alo, r0 * 128, M, tid);
    CP_COMMIT();

    int wid = tid >> 5;
    int lane = tid & 31;
    int m0 = (wid & 3) * 32;
    int n0 = (wid >> 2) * 32;

    int gq = lane >> 3, l8 = lane & 7;
    int fr_row = (gq & 1) * 8 + l8;
    int fr_col = (gq >> 1) * 16;

    uint32_t aoff[2], boff[2];
    #pragma unroll
    for (int mt = 0; mt < 2; ++mt)
        aoff[mt] = (uint32_t)((m0 + mt * 16 + fr_row) * TSTRIDE + fr_col);
    #pragma unroll
    for (int nt2 = 0; nt2 < 2; ++nt2)
        boff[nt2] = (uint32_t)((n0 + nt2 * 16 + fr_row) * TSTRIDE + fr_col);

    int qr = lane >> 2;
    int qc = (lane & 3) * 2;
    float2 bv[4];
    #pragma unroll
    for (int nt = 0; nt < 4; ++nt)
        bv[nt] = *(const float2*)(bias + wc0 + n0 + nt * 8 + qc);

    int buf = 0;
    for (int r = r0; r < nrt; r += stride) {
        int rn = r + stride;
        if (rn < nrt)
            prefetch_A(uA[buf ^ 1][0], uA[buf ^ 1][1], Ahi, Alo, rn * 128, M, tid);
        CP_COMMIT();
        if (rn < nrt) CP_WAIT1(); else CP_WAIT0();
        __syncthreads();

        uint32_t uAhi = uA[buf][0], uAlo = uA[buf][1];

        float c[2][4][4];
        #pragma unroll
        for (int mt = 0; mt < 2; ++mt)
            #pragma unroll
            for (int nt = 0; nt < 4; ++nt)
                #pragma unroll
                for (int q = 0; q < 4; ++q) c[mt][nt][q] = 0.f;

        #pragma unroll
        for (int kk = 0; kk < 8; ++kk) {
            uint32_t ah[2][4], al2[2][4];
            #pragma unroll
            for (int mt = 0; mt < 2; ++mt) {
                LDMX4(ah[mt][0], ah[mt][1], ah[mt][2], ah[mt][3], uAhi + aoff[mt] + kk * 32);
                LDMX4(al2[mt][0], al2[mt][1], al2[mt][2], al2[mt][3], uAlo + aoff[mt] + kk * 32);
            }
            uint32_t bh[2][4], bl[2][4];
            #pragma unroll
            for (int nt2 = 0; nt2 < 2; ++nt2) {
                LDMX4(bh[nt2][0], bh[nt2][1], bh[nt2][2], bh[nt2][3], uBhi + boff[nt2] + kk * 32);
                LDMX4(bl[nt2][0], bl[nt2][1], bl[nt2][2], bl[nt2][3], uBlo + boff[nt2] + kk * 32);
            }
            #pragma unroll
            for (int mt = 0; mt < 2; ++mt)
                #pragma unroll
                for (int nt = 0; nt < 4; ++nt) {
                    int nt2 = nt >> 1, odd = nt & 1;
                    MMA_BF16(c[mt][nt], ah[mt][0], ah[mt][1], ah[mt][2], ah[mt][3],
                             bh[nt2][odd], bh[nt2][2 + odd]);
                    MMA_BF16(c[mt][nt], ah[mt][0], ah[mt][1], ah[mt][2], ah[mt][3],
                             bl[nt2][odd], bl[nt2][2 + odd]);
                    MMA_BF16(c[mt][nt], al2[mt][0], al2[mt][1], al2[mt][2], al2[mt][3],
                             bh[nt2][odd], bh[nt2][2 + odd]);
                }
        }

        int row0 = r * 128;
        #pragma unroll
        for (int mt = 0; mt < 2; ++mt) {
            int r_lo = row0 + m0 + mt * 16 + qr;
            #pragma unroll
            for (int nt = 0; nt < 4; ++nt) {
                int colb = n0 + nt * 8 + qc;
                float2 v0 = make_float2(c[mt][nt][0] + bv[nt].x, c[mt][nt][1] + bv[nt].y);
                float2 v1 = make_float2(c[mt][nt][2] + bv[nt].x, c[mt][nt][3] + bv[nt].y);
                if (do_relu) {
                    v0.x = fmaxf(v0.x, 0.f); v0.y = fmaxf(v0.y, 0.f);
                    v1.x = fmaxf(v1.x, 0.f); v1.y = fmaxf(v1.y, 0.f);
                }
                #pragma unroll
                for (int half = 0; half < 2; ++half) {
                    int rr = r_lo + half * 8;
                    float2 vv = half ? v1 : v0;
                    if (rr < M) {
                        *(float2*)(out + (size_t)rr * ldo + oc + colb) = vv;
                        if (conv_out) {
                            __nv_bfloat16 hx = __float2bfloat16(vv.x);
                            __nv_bfloat16 hy = __float2bfloat16(vv.y);
                            __nv_bfloat16 lx = __float2bfloat16(vv.x - __bfloat162float(hx));
                            __nv_bfloat16 ly = __float2bfloat16(vv.y - __bfloat162float(hy));
                            size_t ai = (size_t)rr * 128 + oc + colb;
                            *(uint32_t*)(g_ahi + ai) = pack_bf2(hx, hy);
                            *(uint32_t*)(g_alo + ai) = pack_bf2(lx, ly);
                        }
                    }
                }
            }
        }
        __syncthreads();
        buf ^= 1;
    }
}

// ===== GATv2 layer-1 (R13 form): one warp per block =====
#define LRD(t, x4, r4, a4) do {                                        \
    float ex = (x4).x + (r4).x; ex = fmaxf(ex, 0.2f * ex); t = fmaf(ex, (a4).x, t); \
    float ey = (x4).y + (r4).y; ey = fmaxf(ey, 0.2f * ey); t = fmaf(ey, (a4).y, t); \
    float ez = (x4).z + (r4).z; ez = fmaxf(ez, 0.2f * ez); t = fmaf(ez, (a4).z, t); \
    float ew = (x4).w + (r4).w; ew = fmaxf(ew, 0.2f * ew); t = fmaf(ew, (a4).w, t); \
} while (0)

__global__ void __launch_bounds__(32)
gat2_k(const float* __restrict__ xlxr,
       const float* __restrict__ hres,
       const float* __restrict__ att,
       const float* __restrict__ gatb,
       const float* __restrict__ lng,
       const float* __restrict__ lnb,
       float* __restrict__ outh,
       int N) {
    int n    = blockIdx.x;
    int lane = threadIdx.x;
    if (n >= N) return;
    int g  = lane >> 3;
    int l8 = lane & 7;
    int cb = g * 32 + l8 * 4;

    float4 atv[4], xrv[4];
    const float4* ap = (const float4*)att + cb;
    const float4* xp = (const float4*)(xlxr + (size_t)n * 1024 + 512) + cb;
    #pragma unroll
    for (int j = 0; j < 4; ++j) { atv[j] = ap[j]; xrv[j] = xp[j]; }

    float m = -CUDART_INF_F, d = 0.f;
    float4 acc[4];
    #pragma unroll
    for (int j = 0; j < 4; ++j) acc[j] = make_float4(0.f, 0.f, 0.f, 0.f);

    int e = g_rp[n], end = g_rp[n + 1];
    for (; e + 2 <= end; e += 2) {
        int s0 = g_csrc[e];
        int s1 = g_csrc[e + 1];
        const float4* q0 = (const float4*)(xlxr + (size_t)s0 * 1024) + cb;
        const float4* q1 = (const float4*)(xlxr + (size_t)s1 * 1024) + cb;
        float4 x0[4], x1[4];
        #pragma unroll
        for (int j = 0; j < 4; ++j) x0[j] = q0[j];
        #pragma unroll
        for (int j = 0; j < 4; ++j) x1[j] = q1[j];

        float t0 = 0.f, t1 = 0.f;
        #pragma unroll
        for (int j = 0; j < 4; ++j) { LRD(t0, x0[j], xrv[j], atv[j]); LRD(t1, x1[j], xrv[j], atv[j]); }
        t0 += __shfl_xor_sync(0xffffffffu, t0, 1);
        t1 += __shfl_xor_sync(0xffffffffu, t1, 1);
        t0 += __shfl_xor_sync(0xffffffffu, t0, 2);
        t1 += __shfl_xor_sync(0xffffffffu, t1, 2);
        t0 += __shfl_xor_sync(0xffffffffu, t0, 4);
        t1 += __shfl_xor_sync(0xffffffffu, t1, 4);

        float mn = fmaxf(m, fmaxf(t0, t1));
        float sc = __expf(m - mn);
        float p0 = __expf(t0 - mn);
        float p1 = __expf(t1 - mn);
        d = fmaf(d, sc, p0 + p1);
        #pragma unroll
        for (int j = 0; j < 4; ++j) {
            acc[j].x = fmaf(acc[j].x, sc, fmaf(p0, x0[j].x, p1 * x1[j].x));
            acc[j].y = fmaf(acc[j].y, sc, fmaf(p0, x0[j].y, p1 * x1[j].y));
            acc[j].z = fmaf(acc[j].z, sc, fmaf(p0, x0[j].z, p1 * x1[j].z));
            acc[j].w = fmaf(acc[j].w, sc, fmaf(p0, x0[j].w, p1 * x1[j].w));
        }
        m = mn;
    }
    if (e < end) {
        int s0 = g_csrc[e];
        const float4* q0 = (const float4*)(xlxr + (size_t)s0 * 1024) + cb;
        float4 x0[4];
        #pragma unroll
        for (int j = 0; j < 4; ++j) x0[j] = q0[j];
        float t0 = 0.f;
        #pragma unroll
        for (int j = 0; j < 4; ++j) LRD(t0, x0[j], xrv[j], atv[j]);
        t0 += __shfl_xor_sync(0xffffffffu, t0, 1);
        t0 += __shfl_xor_sync(0xffffffffu, t0, 2);
        t0 += __shfl_xor_sync(0xffffffffu, t0, 4);
        float mn = fmaxf(m, t0);
        float sc = __expf(m - mn);
        float p0 = __expf(t0 - mn);
        d = fmaf(d, sc, p0);
        #pragma unroll
        for (int j = 0; j < 4; ++j) {
            acc[j].x = fmaf(acc[j].x, sc, p0 * x0[j].x);
            acc[j].y = fmaf(acc[j].y, sc, p0 * x0[j].y);
            acc[j].z = fmaf(acc[j].z, sc, p0 * x0[j].z);
            acc[j].w = fmaf(acc[j].w, sc, p0 * x0[j].w);
        }
        m = mn;
    }

    float inv = 0.25f / d;
    float* a = (float*)acc;
    #pragma unroll
    for (int i = 0; i < 16; ++i) {
        float v = a[i] * inv;
        v += __shfl_xor_sync(0xffffffffu, v, 8);
        v += __shfl_xor_sync(0xffffffffu, v, 16);
        a[i] = v;
    }

    int fb = l8 * 4;
    const float4* gbp = (const float4*)gatb + fb;
    const float4* hrp = (const float4*)(hres + (size_t)n * 128) + fb;
    float4 v4[4];
    float s1 = 0.f, s2 = 0.f;
    #pragma unroll
    for (int j = 0; j < 4; ++j) {
        float4 gb = gbp[j], hr = hrp[j];
        v4[j].x = acc[j].x + gb.x + hr.x;
        v4[j].y = acc[j].y + gb.y + hr.y;
        v4[j].z = acc[j].z + gb.z + hr.z;
        v4[j].w = acc[j].w + gb.w + hr.w;
        s1 += v4[j].x + v4[j].y + v4[j].z + v4[j].w;
        s2 += v4[j].x * v4[j].x + v4[j].y * v4[j].y + v4[j].z * v4[j].z + v4[j].w * v4[j].w;
    }
    s1 += __shfl_xor_sync(0xffffffffu, s1, 1);
    s2 += __shfl_xor_sync(0xffffffffu, s2, 1);
    s1 += __shfl_xor_sync(0xffffffffu, s1, 2);
    s2 += __shfl_xor_sync(0xffffffffu, s2, 2);
    s1 += __shfl_xor_sync(0xffffffffu, s1, 4);
    s2 += __shfl_xor_sync(0xffffffffu, s2, 4);
    float mean = s1 * (1.f / 128.f);
    float var  = s2 * (1.f / 128.f) - mean * mean;
    float rstd = rsqrtf(var + 1e-5f);

    const float4* gp = (const float4*)lng + fb;
    const float4* bp = (const float4*)lnb + fb;
    #pragma unroll
    for (int j = 0; j < 4; ++j) {
        float4 gg = gp[j], bb = bp[j];
        float4 y4;
        y4.x = fmaxf((v4[j].x - mean) * rstd * gg.x + bb.x, 0.f);
        y4.y = fmaxf((v4[j].y - mean) * rstd * gg.y + bb.y, 0.f);
        y4.z = fmaxf((v4[j].z - mean) * rstd * gg.z + bb.z, 0.f);
        y4.w = fmaxf((v4[j].w - mean) * rstd * gg.w + bb.w, 0.f);
        if (g == 0) {
            ((float4*)outh)[(size_t)n * 32 + fb + j] = y4;
            __nv_bfloat16 hx = __float2bfloat16(y4.x);
            __nv_bfloat16 hy = __float2bfloat16(y4.y);
            __nv_bfloat16 hz = __float2bfloat16(y4.z);
            __nv_bfloat16 hw = __float2bfloat16(y4.w);
            __nv_bfloat16 lx = __float2bfloat16(y4.x - __bfloat162float(hx));
            __nv_bfloat16 ly = __float2bfloat16(y4.y - __bfloat162float(hy));
            __nv_bfloat16 lz = __float2bfloat16(y4.z - __bfloat162float(hz));
            __nv_bfloat16 lw = __float2bfloat16(y4.w - __bfloat162float(hw));
            size_t ai = (size_t)n * 32 + fb + j;
            ((uint2*)g_ahi)[ai] = make_uint2(pack_bf2(hx, hy), pack_bf2(hz, hw));
            ((uint2*)g_alo)[ai] = make_uint2(pack_bf2(lx, ly), pack_bf2(lz, lw));
        }
    }
}

// ===== Fused actor+critic GAT: one warp/node, both feature sets per edge =====
__global__ void __launch_bounds__(32)
gatf_k(const float* __restrict__ xla,       // actor xl|xr
       const float* __restrict__ xlk,       // critic xl|xr
       const float* __restrict__ hres,      // h2 residual (shared)
       const float* __restrict__ att_a, const float* __restrict__ att_k,
       const float* __restrict__ gb_a,  const float* __restrict__ gb_k,
       const float* __restrict__ lng_a, const float* __restrict__ lnb_a,
       const float* __restrict__ lng_k, const float* __restrict__ lnb_k,
       const float* __restrict__ hw_a,  const float* __restrict__ hb_a,
       const float* __restrict__ hw_k,  const float* __restrict__ hb_k,
       float* __restrict__ out_a, float* __restrict__ out_k,
       int N) {
    int n    = blockIdx.x;
    int lane = threadIdx.x;
    if (n >= N) return;
    int g  = lane >> 3;
    int l8 = lane & 7;
    int cb = g * 32 + l8 * 4;

    float4 ata[4], xra[4], atk[4], xrk[4];
    {
        const float4* apa = (const float4*)att_a + cb;
        const float4* xpa = (const float4*)(xla + (size_t)n * 1024 + 512) + cb;
        const float4* apk = (const float4*)att_k + cb;
        const float4* xpk = (const float4*)(xlk + (size_t)n * 1024 + 512) + cb;
        #pragma unroll
        for (int j = 0; j < 4; ++j) { ata[j] = apa[j]; xra[j] = xpa[j]; atk[j] = apk[j]; xrk[j] = xpk[j]; }
    }

    float ma = -CUDART_INF_F, da = 0.f;
    float mk = -CUDART_INF_F, dk = 0.f;
    float4 aca[4], ack[4];
    #pragma unroll
    for (int j = 0; j < 4; ++j) {
        aca[j] = make_float4(0.f, 0.f, 0.f, 0.f);
        ack[j] = make_float4(0.f, 0.f, 0.f, 0.f);
    }

    int e = g_rp[n], end = g_rp[n + 1];
    for (; e < end; ++e) {
        int s0 = g_csrc[e];
        const float4* qa = (const float4*)(xla + (size_t)s0 * 1024) + cb;
        const float4* qk = (const float4*)(xlk + (size_t)s0 * 1024) + cb;
        float4 xa[4], xk[4];
        #pragma unroll
        for (int j = 0; j < 4; ++j) xa[j] = qa[j];
        #pragma unroll
        for (int j = 0; j < 4; ++j) xk[j] = qk[j];

        float ta = 0.f, tk = 0.f;
        #pragma unroll
        for (int j = 0; j < 4; ++j) { LRD(ta, xa[j], xra[j], ata[j]); LRD(tk, xk[j], xrk[j], atk[j]); }
        ta += __shfl_xor_sync(0xffffffffu, ta, 1);
        tk += __shfl_xor_sync(0xffffffffu, tk, 1);
        ta += __shfl_xor_sync(0xffffffffu, ta, 2);
        tk += __shfl_xor_sync(0xffffffffu, tk, 2);
        ta += __shfl_xor_sync(0xffffffffu, ta, 4);
        tk += __shfl_xor_sync(0xffffffffu, tk, 4);

        float mna = fmaxf(ma, ta);
        float mnk = fmaxf(mk, tk);
        float sca = __expf(ma - mna);
        float sck = __expf(mk - mnk);
        float pa  = __expf(ta - mna);
        float pk  = __expf(tk - mnk);
        da = fmaf(da, sca, pa);
        dk = fmaf(dk, sck, pk);
        #pragma unroll
        for (int j = 0; j < 4; ++j) {
            aca[j].x = fmaf(aca[j].x, sca, pa * xa[j].x);
            aca[j].y = fmaf(aca[j].y, sca, pa * xa[j].y);
            aca[j].z = fmaf(aca[j].z, sca, pa * xa[j].z);
            aca[j].w = fmaf(aca[j].w, sca, pa * xa[j].w);
            ack[j].x = fmaf(ack[j].x, sck, pk * xk[j].x);
            ack[j].y = fmaf(ack[j].y, sck, pk * xk[j].y);
            ack[j].z = fmaf(ack[j].z, sck, pk * xk[j].z);
            ack[j].w = fmaf(ack[j].w, sck, pk * xk[j].w);
        }
        ma = mna;
        mk = mnk;
    }

    // merge heads for both
    float inva = 0.25f / da, invk = 0.25f / dk;
    float* aa = (float*)aca;
    float* ak = (float*)ack;
    #pragma unroll
    for (int i = 0; i < 16; ++i) {
        float va = aa[i] * inva;
        float vk = ak[i] * invk;
        va += __shfl_xor_sync(0xffffffffu, va, 8);
        vk += __shfl_xor_sync(0xffffffffu, vk, 8);
        va += __shfl_xor_sync(0xffffffffu, va, 16);
        vk += __shfl_xor_sync(0xffffffffu, vk, 16);
        aa[i] = va;
        ak[i] = vk;
    }

    int fb = l8 * 4;
    const float4* hrp = (const float4*)(hres + (size_t)n * 128) + fb;
    float4 hr4[4];
    #pragma unroll
    for (int j = 0; j < 4; ++j) hr4[j] = hrp[j];

    // ---- actor epilogue ----
    {
        const float4* gbp = (const float4*)gb_a + fb;
        float4 v4[4];
        float s1 = 0.f, s2 = 0.f;
        #pragma unroll
        for (int j = 0; j < 4; ++j) {
            float4 gb = gbp[j];
            v4[j].x = aca[j].x + gb.x + hr4[j].x;
            v4[j].y = aca[j].y + gb.y + hr4[j].y;
            v4[j].z = aca[j].z + gb.z + hr4[j].z;
            v4[j].w = aca[j].w + gb.w + hr4[j].w;
            s1 += v4[j].x + v4[j].y + v4[j].z + v4[j].w;
            s2 += v4[j].x * v4[j].x + v4[j].y * v4[j].y + v4[j].z * v4[j].z + v4[j].w * v4[j].w;
        }
        s1 += __shfl_xor_sync(0xffffffffu, s1, 1);
        s2 += __shfl_xor_sync(0xffffffffu, s2, 1);
        s1 += __shfl_xor_sync(0xffffffffu, s1, 2);
        s2 += __shfl_xor_sync(0xffffffffu, s2, 2);
        s1 += __shfl_xor_sync(0xffffffffu, s1, 4);
        s2 += __shfl_xor_sync(0xffffffffu, s2, 4);
        float mean = s1 * (1.f / 128.f);
        float var  = s2 * (1.f / 128.f) - mean * mean;
        float rstd = rsqrtf(var + 1e-5f);
        const float4* gp = (const float4*)lng_a + fb;
        const float4* bp = (const float4*)lnb_a + fb;
        const float4* wp = (const float4*)hw_a + fb;
        float pp = 0.f;
        #pragma unroll
        for (int j = 0; j < 4; ++j) {
            float4 gg = gp[j], bb = bp[j], w4 = wp[j];
            float yx = fmaxf((v4[j].x - mean) * rstd * gg.x + bb.x, 0.f);
            float yy = fmaxf((v4[j].y - mean) * rstd * gg.y + bb.y, 0.f);
            float yz = fmaxf((v4[j].z - mean) * rstd * gg.z + bb.z, 0.f);
            float yw = fmaxf((v4[j].w - mean) * rstd * gg.w + bb.w, 0.f);
            pp = fmaf(yx, w4.x, pp);
            pp = fmaf(yy, w4.y, pp);
            pp = fmaf(yz, w4.z, pp);
            pp = fmaf(yw, w4.w, pp);
        }
        pp += __shfl_xor_sync(0xffffffffu, pp, 1);
        pp += __shfl_xor_sync(0xffffffffu, pp, 2);
        pp += __shfl_xor_sync(0xffffffffu, pp, 4);
        if (lane == 0) out_a[n] = pp + hb_a[0];
    }
    // ---- critic epilogue ----
    {
        const float4* gbp = (const float4*)gb_k + fb;
        float4 v4[4];
        float s1 = 0.f, s2 = 0.f;
        #pragma unroll
        for (int j = 0; j < 4; ++j) {
            float4 gb = gbp[j];
            v4[j].x = ack[j].x + gb.x + hr4[j].x;
            v4[j].y = ack[j].y + gb.y + hr4[j].y;
            v4[j].z = ack[j].z + gb.z + hr4[j].z;
            v4[j].w = ack[j].w + gb.w + hr4[j].w;
            s1 += v4[j].x + v4[j].y + v4[j].z + v4[j].w;
            s2 += v4[j].x * v4[j].x + v4[j].y * v4[j].y + v4[j].z * v4[j].z + v4[j].w * v4[j].w;
        }
        s1 += __shfl_xor_sync(0xffffffffu, s1, 1);
        s2 += __shfl_xor_sync(0xffffffffu, s2, 1);
        s1 += __shfl_xor_sync(0xffffffffu, s1, 2);
        s2 += __shfl_xor_sync(0xffffffffu, s2, 2);
        s1 += __shfl_xor_sync(0xffffffffu, s1, 4);
        s2 += __shfl_xor_sync(0xffffffffu, s2, 4);
        float mean = s1 * (1.f / 128.f);
        float var  = s2 * (1.f / 128.f) - mean * mean;
        float rstd = rsqrtf(var + 1e-5f);
        const float4* gp = (const float4*)lng_k + fb;
        const float4* bp = (const float4*)lnb_k + fb;
        const float4* wp = (const float4*)hw_k + fb;
        float pp = 0.f;
        #pragma unroll
        for (int j = 0; j < 4; ++j) {
            float4 gg = gp[j], bb = bp[j], w4 = wp[j];
            float yx = fmaxf((v4[j].x - mean) * rstd * gg.x + bb.x, 0.f);
            float yy = fmaxf((v4[j].y - mean) * rstd * gg.y + bb.y, 0.f);
            float yz = fmaxf((v4[j].z - mean) * rstd * gg.z + bb.z, 0.f);
            float yw = fmaxf((v4[j].w - mean) * rstd * gg.w + bb.w, 0.f);
            pp = fmaf(yx, w4.x, pp);
            pp = fmaf(yy, w4.y, pp);
            pp = fmaf(yz, w4.z, pp);
            pp = fmaf(yw, w4.w, pp);
        }
        pp += __shfl_xor_sync(0xffffffffu, pp, 1);
        pp += __shfl_xor_sync(0xffffffffu, pp, 2);
        pp += __shfl_xor_sync(0xffffffffu, pp, 4);
        if (lane == 0) out_k[n] = pp + hb_k[0];
    }
}

// ---------------- launch ----------------
extern "C" void kernel_launch(void* const* d_in, const int* in_sizes, int n_in,
                              void* d_out, int out_size) {
    const float* x     = (const float*)d_in[0];
    const int*   ei    = (const int*)d_in[1];
    const float* W_in  = (const float*)d_in[2];
    const float* b_in  = (const float*)d_in[3];
    const float* c1_Wl = (const float*)d_in[4];
    const float* c1_bl = (const float*)d_in[5];
    const float* c1_Wr = (const float*)d_in[6];
    const float* c1_br = (const float*)d_in[7];
    const float* c1_att= (const float*)d_in[8];
    const float* c1_b  = (const float*)d_in[9];
    const float* ln1_g = (const float*)d_in[10];
    const float* ln1_b = (const float*)d_in[11];
    const float* a_Wl  = (const float*)d_in[12];
    const float* a_bl  = (const float*)d_in[13];
    const float* a_Wr  = (const float*)d_in[14];
    const float* a_br  = (const float*)d_in[15];
    const float* a_att = (const float*)d_in[16];
    const float* a_b   = (const float*)d_in[17];
    const float* aln_g = (const float*)d_in[18];
    const float* aln_b = (const float*)d_in[19];
    const float* ah_W  = (const float*)d_in[20];
    const float* ah_b  = (const float*)d_in[21];
    const float* k_Wl  = (const float*)d_in[22];
    const float* k_bl  = (const float*)d_in[23];
    const float* k_Wr  = (const float*)d_in[24];
    const float* k_br  = (const float*)d_in[25];
    const float* k_att = (const float*)d_in[26];
    const float* k_b   = (const float*)d_in[27];
    const float* kln_g = (const float*)d_in[28];
    const float* kln_b = (const float*)d_in[29];
    const float* kh_W  = (const float*)d_in[30];
    const float* kh_b  = (const float*)d_in[31];

    int N = in_sizes[0] / 128;
    int E = in_sizes[1] / 2;
    float* out = (float*)d_out;

    float *h1, *h2, *xlxr, *xlxr2, *biasc;
    __nv_bfloat16 *ahi, *alo, *wthi, *wtlo;
    cudaGetSymbolAddress((void**)&h1, g_h1);
    cudaGetSymbolAddress((void**)&h2, g_h2);
    cudaGetSymbolAddress((void**)&xlxr, g_xlxr);
    cudaGetSymbolAddress((void**)&xlxr2, g_xlxr2);
    cudaGetSymbolAddress((void**)&biasc, g_biasc);
    cudaGetSymbolAddress((void**)&ahi, g_ahi);
    cudaGetSymbolAddress((void**)&alo, g_alo);
    cudaGetSymbolAddress((void**)&wthi, g_wthi);
    cudaGetSymbolAddress((void**)&wtlo, g_wtlo);

    cudaFuncSetAttribute(gemm_mma_k, cudaFuncAttributeMaxDynamicSharedMemorySize, GMM_SMEM);

    int gc = (N * 32 + 255) / 256;
    const int NOSPLIT = 1 << 30;

    conv_all_k<<<(2048 + 6 * 8192 + WT_ROWS + 255) / 256, 256>>>(          // 1
        W_in, c1_Wl, c1_Wr, a_Wl, a_Wr, k_Wl, k_Wr,
        b_in, c1_bl, c1_br, a_bl, a_br, k_bl, k_br, N);
    conv_a_k<<<gc, 256>>>(x, N * 32);                                      // 2
    gemm_mma_k<<<dim3(148, 1), 512, GMM_SMEM>>>(ahi, alo, N,               // 3: input layer
        wthi, wtlo, biasc, h1, (float*)0, NOSPLIT, 128, 1, 1);
    gemm_mma_k<<<dim3(18, 8), 512, GMM_SMEM>>>(ahi, alo, N,                // 4 <- profiled
        wthi + (size_t)128 * 128, wtlo + (size_t)128 * 128, biasc + 128,
        xlxr, (float*)0, NOSPLIT, 1024, 0, 0);

    count_k<<<(E + 255) / 256, 256>>>(ei + E, E);                          // 5
    scan2_k<<<1, 1024>>>(N);                                               // 6
    scatter_k<<<(E + N + 255) / 256, 256>>>(ei, ei + E, E, N);             // 7

    gat2_k<<<N, 32>>>(xlxr, h1, c1_att, c1_b, ln1_g, ln1_b, h2, N);        // 8

    gemm_mma_k<<<dim3(9, 16), 512, GMM_SMEM>>>(ahi, alo, N,                // 9
        wthi + (size_t)1152 * 128, wtlo + (size_t)1152 * 128, biasc + 1152,
        xlxr, xlxr2, 1024, 1024, 0, 0);

    gatf_k<<<N, 32>>>(xlxr, xlxr2, h2,                                     // 10: fused actor+critic
                      a_att, k_att, a_b, k_b,
                      aln_g, aln_b, kln_g, kln_b,
                      ah_W, ah_b, kh_W, kh_b,
                      out, out + N, N);
}

// round 15
// speedup vs baseline: 1.3362x; 1.2375x over previous
#include <cuda_runtime.h>
#include <cuda_bf16.h>
#include <cuda_fp16.h>
#include <math_constants.h>
#include <cstdint>

// Problem constants (fixed dataset shapes)
#define NMAX 20000
#define EMAX 320000
#define ETOT (EMAX + NMAX)

// ---------------- device scratch (static allocations only) ----------------
__device__ float  g_h1[(size_t)NMAX * 128];
__device__ float  g_h2[(size_t)NMAX * 128];
__device__ __half g_xlxr[(size_t)NMAX * 1024];    // layer1 & actor: [xl(512) | xr(512)] fp16
__device__ __half g_xlxr2[(size_t)NMAX * 1024];   // critic, fp16
__device__ int    g_cnt[NMAX];
__device__ int    g_rp[NMAX + 1];
__device__ int    g_cur[NMAX];
__device__ int    g_csrc[ETOT];

// bf16 hi/lo activations
__device__ __nv_bfloat16 g_ahi[(size_t)NMAX * 128];
__device__ __nv_bfloat16 g_alo[(size_t)NMAX * 128];
// transposed bf16 hi/lo weights: rows = 128(W_in) + 6*512 = 3200, each row 128 bf16
#define WT_ROWS 3200
__device__ __nv_bfloat16 g_wthi[(size_t)WT_ROWS * 128];
__device__ __nv_bfloat16 g_wtlo[(size_t)WT_ROWS * 128];
// packed biases, index-matched to wt rows
__device__ float g_biasc[WT_ROWS];

// ---------------- CSR build ----------------
__global__ void count_k(const int* __restrict__ dstv, int E) {
    int i = blockIdx.x * blockDim.x + threadIdx.x;
    if (i < E) atomicAdd(&g_cnt[dstv[i]], 1);
}
__global__ void scan2_k(int N) {
    __shared__ int wsum[32];
    int tid = threadIdx.x;
    int lane = tid & 31, wid = tid >> 5;
    int per = (N + 1023) >> 10;
    int start = tid * per;
    int s = 0;
    for (int i = 0; i < per; ++i) {
        int idx = start + i;
        if (idx < N) s += g_cnt[idx];
    }
    int v = s;
    #pragma unroll
    for (int off = 1; off < 32; off <<= 1) {
        int t = __shfl_up_sync(0xffffffffu, v, off);
        if (lane >= off) v += t;
    }
    if (lane == 31) wsum[wid] = v;
    __syncthreads();
    if (wid == 0) {
        int w = wsum[lane];
        #pragma unroll
        for (int off = 1; off < 32; off <<= 1) {
            int t = __shfl_up_sync(0xffffffffu, w, off);
            if (lane >= off) w += t;
        }
        wsum[lane] = w;
    }
    __syncthreads();
    int excl = v - s + (wid ? wsum[wid - 1] : 0);
    int run = excl;
    for (int i = 0; i < per; ++i) {
        int idx = start + i;
        if (idx < N) {
            int c = g_cnt[idx];
            g_cur[idx] = run;
            run += c;
            g_rp[idx + 1] = run;
        }
    }
    if (tid == 0) g_rp[0] = 0;
}
__global__ void scatter_k(const int* __restrict__ srcv, const int* __restrict__ dstv,
                          int E, int N) {
    int i = blockIdx.x * blockDim.x + threadIdx.x;
    if (i < E) {
        int d = dstv[i];
        int pos = atomicAdd(&g_cur[d], 1);
        g_csrc[pos] = srcv[i];
    } else if (i < E + N) {
        int n = i - E;
        int pos = atomicAdd(&g_cur[n], 1);
        g_csrc[pos] = n;
    }
}

// ---------------- weights transpose + hi/lo + bias pack + cnt init, ONE launch ----------------
__device__ __forceinline__ uint32_t pack_bf2(__nv_bfloat16 a, __nv_bfloat16 b) {
    return (uint32_t)__bfloat16_as_ushort(a) | ((uint32_t)__bfloat16_as_ushort(b) << 16);
}

__global__ void conv_all_k(const float* __restrict__ w0, const float* __restrict__ w1,
                           const float* __restrict__ w2, const float* __restrict__ w3,
                           const float* __restrict__ w4, const float* __restrict__ w5,
                           const float* __restrict__ w6,
                           const float* __restrict__ b0, const float* __restrict__ b1,
                           const float* __restrict__ b2, const float* __restrict__ b3,
                           const float* __restrict__ b4, const float* __restrict__ b5,
                           const float* __restrict__ b6, int N) {
    int i = blockIdx.x * blockDim.x + threadIdx.x;
    if (i < N) g_cnt[i] = 1;   // self-loop pre-count
    const int WTH = 2048 + 6 * 8192;   // 51200
    if (i < WTH) {
        const float* W; int cols, rowoff, n, kg;
        if (i < 2048) { W = w0; cols = 128; rowoff = 0; n = i & 127; kg = i >> 7; }
        else {
            int j = i - 2048;
            int s = j >> 13;
            int r = j & 8191;
            n = r & 511; kg = r >> 9;
            W = (s == 0) ? w1 : (s == 1) ? w2 : (s == 2) ? w3 : (s == 3) ? w4 : (s == 4) ? w5 : w6;
            cols = 512; rowoff = 128 + s * 512;
        }
        int k0 = kg * 8;
        __nv_bfloat16 h8[8], l8v[8];
        #pragma unroll
        for (int q = 0; q < 8; ++q) {
            float v = W[(size_t)(k0 + q) * cols + n];
            __nv_bfloat16 h = __float2bfloat16(v);
            h8[q] = h;
            l8v[q] = __float2bfloat16(v - __bfloat162float(h));
        }
        uint4 hv, lv;
        hv.x = pack_bf2(h8[0], h8[1]); hv.y = pack_bf2(h8[2], h8[3]);
        hv.z = pack_bf2(h8[4], h8[5]); hv.w = pack_bf2(h8[6], h8[7]);
        lv.x = pack_bf2(l8v[0], l8v[1]); lv.y = pack_bf2(l8v[2], l8v[3]);
        lv.z = pack_bf2(l8v[4], l8v[5]); lv.w = pack_bf2(l8v[6], l8v[7]);
        *(uint4*)(g_wthi + (size_t)(rowoff + n) * 128 + k0) = hv;
        *(uint4*)(g_wtlo + (size_t)(rowoff + n) * 128 + k0) = lv;
    } else if (i < WTH + WT_ROWS) {
        int j = i - WTH;
        float v;
        if (j < 128) v = b0[j];
        else {
            int s = (j - 128) >> 9, t = (j - 128) & 511;
            const float* B = (s == 0) ? b1 : (s == 1) ? b2 : (s == 2) ? b3
                           : (s == 3) ? b4 : (s == 4) ? b5 : b6;
            v = B[t];
        }
        g_biasc[j] = v;
    }
}

// ---------------- activation fp32 -> bf16 hi/lo (x only) ----------------
__global__ void conv_a_k(const float* __restrict__ src, int n4) {
    int i = blockIdx.x * blockDim.x + threadIdx.x;
    if (i < n4) {
        float4 v = ((const float4*)src)[i];
        __nv_bfloat16 hx = __float2bfloat16(v.x);
        __nv_bfloat16 hy = __float2bfloat16(v.y);
        __nv_bfloat16 hz = __float2bfloat16(v.z);
        __nv_bfloat16 hw = __float2bfloat16(v.w);
        __nv_bfloat16 lx = __float2bfloat16(v.x - __bfloat162float(hx));
        __nv_bfloat16 ly = __float2bfloat16(v.y - __bfloat162float(hy));
        __nv_bfloat16 lz = __float2bfloat16(v.z - __bfloat162float(hz));
        __nv_bfloat16 lw = __float2bfloat16(v.w - __bfloat162float(hw));
        ((uint2*)g_ahi)[i] = make_uint2(pack_bf2(hx, hy), pack_bf2(hz, hw));
        ((uint2*)g_alo)[i] = make_uint2(pack_bf2(lx, ly), pack_bf2(lz, lw));
    }
}

// ======== bf16x3 GEMM v4: persistent col tile, double-buffered A, 512 threads ========
#define TSTRIDE 272
#define TILE_B (128 * TSTRIDE)
#define GMM_SMEM (6 * TILE_B)

__device__ __forceinline__ uint32_t smem_u32(const void* p) {
    uint32_t a;
    asm("{ .reg .u64 t; cvta.to.shared.u64 t, %1; cvt.u32.u64 %0, t; }" : "=r"(a) : "l"(p));
    return a;
}

#define CP16(dst, src, sz) \
    asm volatile("cp.async.cg.shared.global [%0], [%1], 16, %2;" \
                 :: "r"(dst), "l"(src), "r"(sz) : "memory")
#define CP_COMMIT() asm volatile("cp.async.commit_group;" ::: "memory")
#define CP_WAIT0()  asm volatile("cp.async.wait_group 0;" ::: "memory")
#define CP_WAIT1()  asm volatile("cp.async.wait_group 1;" ::: "memory")

#define LDMX4(r0, r1, r2, r3, addr) \
    asm volatile("ldmatrix.sync.aligned.m8n8.x4.shared.b16 {%0,%1,%2,%3}, [%4];" \
                 : "=r"(r0), "=r"(r1), "=r"(r2), "=r"(r3) : "r"(addr))

#define MMA_BF16(c, a0, a1, a2, a3, b0, b1) \
    asm volatile("mma.sync.aligned.m16n8k16.row.col.f32.bf16.bf16.f32 " \
                 "{%0,%1,%2,%3}, {%4,%5,%6,%7}, {%8,%9}, {%0,%1,%2,%3};" \
                 : "+f"((c)[0]), "+f"((c)[1]), "+f"((c)[2]), "+f"((c)[3]) \
                 : "r"(a0), "r"(a1), "r"(a2), "r"(a3), "r"(b0), "r"(b1))

__device__ __forceinline__ void prefetch_A(uint32_t uAhi, uint32_t uAlo,
                                           const __nv_bfloat16* Ahi, const __nv_bfloat16* Alo,
                                           int row0, int M, int tid) {
    #pragma unroll
    for (int it = 0; it < 4; ++it) {
        int idx = it * 512 + tid;
        int row = idx >> 4, c = idx & 15;
        int grow = row0 + row;
        int ok = grow < M;
        int srow = ok ? grow : 0;
        uint32_t sz = ok ? 16u : 0u;
        CP16(uAhi + row * TSTRIDE + c * 16,
             (const char*)(Ahi + (size_t)srow * 128) + c * 16, sz);
        CP16(uAlo + row * TSTRIDE + c * 16,
             (const char*)(Alo + (size_t)srow * 128) + c * 16, sz);
    }
}

__global__ void __launch_bounds__(512, 1)
gemm_mma_k(const __nv_bfloat16* __restrict__ Ahi, const __nv_bfloat16* __restrict__ Alo, int M,
           const __nv_bfloat16* __restrict__ Bhi, const __nv_bfloat16* __restrict__ Blo,
           const float* __restrict__ bias,
           float* __restrict__ out, float* __restrict__ out2, int split,
           int ldo, int do_relu, int conv_out, int store_half) {
    extern __shared__ char sm[];
    char* sBhi = sm;
    char* sBlo = sm + TILE_B;
    char* sA[2][2];
    sA[0][0] = sm + 2 * TILE_B;
    sA[0][1] = sm + 3 * TILE_B;
    sA[1][0] = sm + 4 * TILE_B;
    sA[1][1] = sm + 5 * TILE_B;

    int tid = threadIdx.x;
    int wc0 = blockIdx.y * 128;
    int oc  = wc0;
    if (oc >= split) { out = out2; oc -= split; }

    uint32_t uBhi = smem_u32(sBhi), uBlo = smem_u32(sBlo);
    uint32_t uA[2][2];
    #pragma unroll
    for (int s = 0; s < 2; ++s) { uA[s][0] = smem_u32(sA[s][0]); uA[s][1] = smem_u32(sA[s][1]); }

    #pragma unroll
    for (int it = 0; it < 4; ++it) {
        int idx = it * 512 + tid;
        int row = idx >> 4, c = idx & 15;
        CP16(uBhi + row * TSTRIDE + c * 16,
             (const char*)(Bhi + (size_t)(wc0 + row) * 128) + c * 16, 16u);
        CP16(uBlo + row * TSTRIDE + c * 16,
             (const char*)(Blo + (size_t)(wc0 + row) * 128) + c * 16, 16u);
    }
    int nrt = (M + 127) >> 7;
    int stride = gridDim.x;
    int r0 = blockIdx.x;
    if (r0 < nrt)
        prefetch_A(uA[0][0], uA[0][1], Ahi, Alo, r0 * 128, M, tid);
    CP_COMMIT();

    int wid = tid >> 5;
    int lane = tid & 31;
    int m0 = (wid & 3) * 32;
    int n0 = (wid >> 2) * 32;

    int gq = lane >> 3, l8 = lane & 7;
    int fr_row = (gq & 1) * 8 + l8;
    int fr_col = (gq >> 1) * 16;

    uint32_t aoff[2], boff[2];
    #pragma unroll
    for (int mt = 0; mt < 2; ++mt)
        aoff[mt] = (uint32_t)((m0 + mt * 16 + fr_row) * TSTRIDE + fr_col);
    #pragma unroll
    for (int nt2 = 0; nt2 < 2; ++nt2)
        boff[nt2] = (uint32_t)((n0 + nt2 * 16 + fr_row) * TSTRIDE + fr_col);

    int qr = lane >> 2;
    int qc = (lane & 3) * 2;
    float2 bv[4];
    #pragma unroll
    for (int nt = 0; nt < 4; ++nt)
        bv[nt] = *(const float2*)(bias + wc0 + n0 + nt * 8 + qc);

    int buf = 0;
    for (int r = r0; r < nrt; r += stride) {
        int rn = r + stride;
        if (rn < nrt)
            prefetch_A(uA[buf ^ 1][0], uA[buf ^ 1][1], Ahi, Alo, rn * 128, M, tid);
        CP_COMMIT();
        if (rn < nrt) CP_WAIT1(); else CP_WAIT0();
        __syncthreads();

        uint32_t uAhi = uA[buf][0], uAlo = uA[buf][1];

        float c[2][4][4];
        #pragma unroll
        for (int mt = 0; mt < 2; ++mt)
            #pragma unroll
            for (int nt = 0; nt < 4; ++nt)
                #pragma unroll
                for (int q = 0; q < 4; ++q) c[mt][nt][q] = 0.f;

        #pragma unroll
        for (int kk = 0; kk < 8; ++kk) {
            uint32_t ah[2][4], al2[2][4];
            #pragma unroll
            for (int mt = 0; mt < 2; ++mt) {
                LDMX4(ah[mt][0], ah[mt][1], ah[mt][2], ah[mt][3], uAhi + aoff[mt] + kk * 32);
                LDMX4(al2[mt][0], al2[mt][1], al2[mt][2], al2[mt][3], uAlo + aoff[mt] + kk * 32);
            }
            uint32_t bh[2][4], bl[2][4];
            #pragma unroll
            for (int nt2 = 0; nt2 < 2; ++nt2) {
                LDMX4(bh[nt2][0], bh[nt2][1], bh[nt2][2], bh[nt2][3], uBhi + boff[nt2] + kk * 32);
                LDMX4(bl[nt2][0], bl[nt2][1], bl[nt2][2], bl[nt2][3], uBlo + boff[nt2] + kk * 32);
            }
            #pragma unroll
            for (int mt = 0; mt < 2; ++mt)
                #pragma unroll
                for (int nt = 0; nt < 4; ++nt) {
                    int nt2 = nt >> 1, odd = nt & 1;
                    MMA_BF16(c[mt][nt], ah[mt][0], ah[mt][1], ah[mt][2], ah[mt][3],
                             bh[nt2][odd], bh[nt2][2 + odd]);
                    MMA_BF16(c[mt][nt], ah[mt][0], ah[mt][1], ah[mt][2], ah[mt][3],
                             bl[nt2][odd], bl[nt2][2 + odd]);
                    MMA_BF16(c[mt][nt], al2[mt][0], al2[mt][1], al2[mt][2], al2[mt][3],
                             bh[nt2][odd], bh[nt2][2 + odd]);
                }
        }

        int row0 = r * 128;
        #pragma unroll
        for (int mt = 0; mt < 2; ++mt) {
            int r_lo = row0 + m0 + mt * 16 + qr;
            #pragma unroll
            for (int nt = 0; nt < 4; ++nt) {
                int colb = n0 + nt * 8 + qc;
                float2 v0 = make_float2(c[mt][nt][0] + bv[nt].x, c[mt][nt][1] + bv[nt].y);
                float2 v1 = make_float2(c[mt][nt][2] + bv[nt].x, c[mt][nt][3] + bv[nt].y);
                if (do_relu) {
                    v0.x = fmaxf(v0.x, 0.f); v0.y = fmaxf(v0.y, 0.f);
                    v1.x = fmaxf(v1.x, 0.f); v1.y = fmaxf(v1.y, 0.f);
                }
                #pragma unroll
                for (int half = 0; half < 2; ++half) {
                    int rr = r_lo + half * 8;
                    float2 vv = half ? v1 : v0;
                    if (rr < M) {
                        if (store_half) {
                            __half2 hv = __floats2half2_rn(vv.x, vv.y);
                            *(__half2*)((__half*)out + (size_t)rr * ldo + oc + colb) = hv;
                        } else {
                            *(float2*)(out + (size_t)rr * ldo + oc + colb) = vv;
                            if (conv_out) {
                                __nv_bfloat16 hx = __float2bfloat16(vv.x);
                                __nv_bfloat16 hy = __float2bfloat16(vv.y);
                                __nv_bfloat16 lx = __float2bfloat16(vv.x - __bfloat162float(hx));
                                __nv_bfloat16 ly = __float2bfloat16(vv.y - __bfloat162float(hy));
                                size_t ai = (size_t)rr * 128 + oc + colb;
                                *(uint32_t*)(g_ahi + ai) = pack_bf2(hx, hy);
                                *(uint32_t*)(g_alo + ai) = pack_bf2(lx, ly);
                            }
                        }
                    }
                }
            }
        }
        __syncthreads();
        buf ^= 1;
    }
}

// ---------------- fp16 feature load: 16 halfs -> 4 float4 ----------------
__device__ __forceinline__ void ldh16(const __half* base, int cbh, float4 x[4]) {
    const uint4* p = (const uint4*)base;
    uint4 v0 = p[cbh];
    uint4 v1 = p[cbh + 1];
    float2 a;
    a = __half22float2(*(const __half2*)&v0.x); x[0].x = a.x; x[0].y = a.y;
    a = __half22float2(*(const __half2*)&v0.y); x[0].z = a.x; x[0].w = a.y;
    a = __half22float2(*(const __half2*)&v0.z); x[1].x = a.x; x[1].y = a.y;
    a = __half22float2(*(const __half2*)&v0.w); x[1].z = a.x; x[1].w = a.y;
    a = __half22float2(*(const __half2*)&v1.x); x[2].x = a.x; x[2].y = a.y;
    a = __half22float2(*(const __half2*)&v1.y); x[2].z = a.x; x[2].w = a.y;
    a = __half22float2(*(const __half2*)&v1.z); x[3].x = a.x; x[3].y = a.y;
    a = __half22float2(*(const __half2*)&v1.w); x[3].z = a.x; x[3].w = a.y;
}

// ===== GATv2 layer-1: one warp per block, fp16 feature gather =====
#define LRD(t, x4, r4, a4) do {                                        \
    float ex = (x4).x + (r4).x; ex = fmaxf(ex, 0.2f * ex); t = fmaf(ex, (a4).x, t); \
    float ey = (x4).y + (r4).y; ey = fmaxf(ey, 0.2f * ey); t = fmaf(ey, (a4).y, t); \
    float ez = (x4).z + (r4).z; ez = fmaxf(ez, 0.2f * ez); t = fmaf(ez, (a4).z, t); \
    float ew = (x4).w + (r4).w; ew = fmaxf(ew, 0.2f * ew); t = fmaf(ew, (a4).w, t); \
} while (0)

__global__ void __launch_bounds__(32)
gat2_k(const __half* __restrict__ xlxr,
       const float* __restrict__ hres,
       const float* __restrict__ att,
       const float* __restrict__ gatb,
       const float* __restrict__ lng,
       const float* __restrict__ lnb,
       float* __restrict__ outh,
       int N) {
    int n    = blockIdx.x;
    int lane = threadIdx.x;
    if (n >= N) return;
    int g  = lane >> 3;
    int l8 = lane & 7;
    int cb = g * 32 + l8 * 4;      // float4 index within 512 channels
    int cbh = cb >> 1;             // uint4(8-half) index

    float4 atv[4], xrv[4];
    const float4* ap = (const float4*)att + cb;
    #pragma unroll
    for (int j = 0; j < 4; ++j) atv[j] = ap[j];
    ldh16(xlxr + (size_t)n * 1024 + 512, cbh, xrv);

    float m = -CUDART_INF_F, d = 0.f;
    float4 acc[4];
    #pragma unroll
    for (int j = 0; j < 4; ++j) acc[j] = make_float4(0.f, 0.f, 0.f, 0.f);

    int e = g_rp[n], end = g_rp[n + 1];
    for (; e + 2 <= end; e += 2) {
        int s0 = g_csrc[e];
        int s1 = g_csrc[e + 1];
        float4 x0[4], x1[4];
        ldh16(xlxr + (size_t)s0 * 1024, cbh, x0);
        ldh16(xlxr + (size_t)s1 * 1024, cbh, x1);

        float t0 = 0.f, t1 = 0.f;
        #pragma unroll
        for (int j = 0; j < 4; ++j) { LRD(t0, x0[j], xrv[j], atv[j]); LRD(t1, x1[j], xrv[j], atv[j]); }
        t0 += __shfl_xor_sync(0xffffffffu, t0, 1);
        t1 += __shfl_xor_sync(0xffffffffu, t1, 1);
        t0 += __shfl_xor_sync(0xffffffffu, t0, 2);
        t1 += __shfl_xor_sync(0xffffffffu, t1, 2);
        t0 += __shfl_xor_sync(0xffffffffu, t0, 4);
        t1 += __shfl_xor_sync(0xffffffffu, t1, 4);

        float mn = fmaxf(m, fmaxf(t0, t1));
        float sc = __expf(m - mn);
        float p0 = __expf(t0 - mn);
        float p1 = __expf(t1 - mn);
        d = fmaf(d, sc, p0 + p1);
        #pragma unroll
        for (int j = 0; j < 4; ++j) {
            acc[j].x = fmaf(acc[j].x, sc, fmaf(p0, x0[j].x, p1 * x1[j].x));
            acc[j].y = fmaf(acc[j].y, sc, fmaf(p0, x0[j].y, p1 * x1[j].y));
            acc[j].z = fmaf(acc[j].z, sc, fmaf(p0, x0[j].z, p1 * x1[j].z));
            acc[j].w = fmaf(acc[j].w, sc, fmaf(p0, x0[j].w, p1 * x1[j].w));
        }
        m = mn;
    }
    if (e < end) {
        int s0 = g_csrc[e];
        float4 x0[4];
        ldh16(xlxr + (size_t)s0 * 1024, cbh, x0);
        float t0 = 0.f;
        #pragma unroll
        for (int j = 0; j < 4; ++j) LRD(t0, x0[j], xrv[j], atv[j]);
        t0 += __shfl_xor_sync(0xffffffffu, t0, 1);
        t0 += __shfl_xor_sync(0xffffffffu, t0, 2);
        t0 += __shfl_xor_sync(0xffffffffu, t0, 4);
        float mn = fmaxf(m, t0);
        float sc = __expf(m - mn);
        float p0 = __expf(t0 - mn);
        d = fmaf(d, sc, p0);
        #pragma unroll
        for (int j = 0; j < 4; ++j) {
            acc[j].x = fmaf(acc[j].x, sc, p0 * x0[j].x);
            acc[j].y = fmaf(acc[j].y, sc, p0 * x0[j].y);
            acc[j].z = fmaf(acc[j].z, sc, p0 * x0[j].z);
            acc[j].w = fmaf(acc[j].w, sc, p0 * x0[j].w);
        }
        m = mn;
    }

    float inv = 0.25f / d;
    float* a = (float*)acc;
    #pragma unroll
    for (int i = 0; i < 16; ++i) {
        float v = a[i] * inv;
        v += __shfl_xor_sync(0xffffffffu, v, 8);
        v += __shfl_xor_sync(0xffffffffu, v, 16);
        a[i] = v;
    }

    int fb = l8 * 4;
    const float4* gbp = (const float4*)gatb + fb;
    const float4* hrp = (const float4*)(hres + (size_t)n * 128) + fb;
    float4 v4[4];
    float s1 = 0.f, s2 = 0.f;
    #pragma unroll
    for (int j = 0; j < 4; ++j) {
        float4 gb = gbp[j], hr = hrp[j];
        v4[j].x = acc[j].x + gb.x + hr.x;
        v4[j].y = acc[j].y + gb.y + hr.y;
        v4[j].z = acc[j].z + gb.z + hr.z;
        v4[j].w = acc[j].w + gb.w + hr.w;
        s1 += v4[j].x + v4[j].y + v4[j].z + v4[j].w;
        s2 += v4[j].x * v4[j].x + v4[j].y * v4[j].y + v4[j].z * v4[j].z + v4[j].w * v4[j].w;
    }
    s1 += __shfl_xor_sync(0xffffffffu, s1, 1);
    s2 += __shfl_xor_sync(0xffffffffu, s2, 1);
    s1 += __shfl_xor_sync(0xffffffffu, s1, 2);
    s2 += __shfl_xor_sync(0xffffffffu, s2, 2);
    s1 += __shfl_xor_sync(0xffffffffu, s1, 4);
    s2 += __shfl_xor_sync(0xffffffffu, s2, 4);
    float mean = s1 * (1.f / 128.f);
    float var  = s2 * (1.f / 128.f) - mean * mean;
    float rstd = rsqrtf(var + 1e-5f);

    const float4* gp = (const float4*)lng + fb;
    const float4* bp = (const float4*)lnb + fb;
    #pragma unroll
    for (int j = 0; j < 4; ++j) {
        float4 gg = gp[j], bb = bp[j];
        float4 y4;
        y4.x = fmaxf((v4[j].x - mean) * rstd * gg.x + bb.x, 0.f);
        y4.y = fmaxf((v4[j].y - mean) * rstd * gg.y + bb.y, 0.f);
        y4.z = fmaxf((v4[j].z - mean) * rstd * gg.z + bb.z, 0.f);
        y4.w = fmaxf((v4[j].w - mean) * rstd * gg.w + bb.w, 0.f);
        if (g == 0) {
            ((float4*)outh)[(size_t)n * 32 + fb + j] = y4;
            __nv_bfloat16 hx = __float2bfloat16(y4.x);
            __nv_bfloat16 hy = __float2bfloat16(y4.y);
            __nv_bfloat16 hz = __float2bfloat16(y4.z);
            __nv_bfloat16 hw = __float2bfloat16(y4.w);
            __nv_bfloat16 lx = __float2bfloat16(y4.x - __bfloat162float(hx));
            __nv_bfloat16 ly = __float2bfloat16(y4.y - __bfloat162float(hy));
            __nv_bfloat16 lz = __float2bfloat16(y4.z - __bfloat162float(hz));
            __nv_bfloat16 lw = __float2bfloat16(y4.w - __bfloat162float(hw));
            size_t ai = (size_t)n * 32 + fb + j;
            ((uint2*)g_ahi)[ai] = make_uint2(pack_bf2(hx, hy), pack_bf2(hz, hw));
            ((uint2*)g_alo)[ai] = make_uint2(pack_bf2(lx, ly), pack_bf2(lz, lw));
        }
    }
}

// ===== Fused actor+critic GAT: one warp/node, fp16 features =====
__global__ void __launch_bounds__(32)
gatf_k(const __half* __restrict__ xla,
       const __half* __restrict__ xlk,
       const float* __restrict__ hres,
       const float* __restrict__ att_a, const float* __restrict__ att_k,
       const float* __restrict__ gb_a,  const float* __restrict__ gb_k,
       const float* __restrict__ lng_a, const float* __restrict__ lnb_a,
       const float* __restrict__ lng_k, const float* __restrict__ lnb_k,
       const float* __restrict__ hw_a,  const float* __restrict__ hb_a,
       const float* __restrict__ hw_k,  const float* __restrict__ hb_k,
       float* __restrict__ out_a, float* __restrict__ out_k,
       int N) {
    int n    = blockIdx.x;
    int lane = threadIdx.x;
    if (n >= N) return;
    int g  = lane >> 3;
    int l8 = lane & 7;
    int cb = g * 32 + l8 * 4;
    int cbh = cb >> 1;

    float4 ata[4], xra[4], atk[4], xrk[4];
    {
        const float4* apa = (const float4*)att_a + cb;
        const float4* apk = (const float4*)att_k + cb;
        #pragma unroll
        for (int j = 0; j < 4; ++j) { ata[j] = apa[j]; atk[j] = apk[j]; }
        ldh16(xla + (size_t)n * 1024 + 512, cbh, xra);
        ldh16(xlk + (size_t)n * 1024 + 512, cbh, xrk);
    }

    float ma = -CUDART_INF_F, da = 0.f;
    float mk = -CUDART_INF_F, dk = 0.f;
    float4 aca[4], ack[4];
    #pragma unroll
    for (int j = 0; j < 4; ++j) {
        aca[j] = make_float4(0.f, 0.f, 0.f, 0.f);
        ack[j] = make_float4(0.f, 0.f, 0.f, 0.f);
    }

    int e = g_rp[n], end = g_rp[n + 1];
    for (; e < end; ++e) {
        int s0 = g_csrc[e];
        float4 xa[4], xk[4];
        ldh16(xla + (size_t)s0 * 1024, cbh, xa);
        ldh16(xlk + (size_t)s0 * 1024, cbh, xk);

        float ta = 0.f, tk = 0.f;
        #pragma unroll
        for (int j = 0; j < 4; ++j) { LRD(ta, xa[j], xra[j], ata[j]); LRD(tk, xk[j], xrk[j], atk[j]); }
        ta += __shfl_xor_sync(0xffffffffu, ta, 1);
        tk += __shfl_xor_sync(0xffffffffu, tk, 1);
        ta += __shfl_xor_sync(0xffffffffu, ta, 2);
        tk += __shfl_xor_sync(0xffffffffu, tk, 2);
        ta += __shfl_xor_sync(0xffffffffu, ta, 4);
        tk += __shfl_xor_sync(0xffffffffu, tk, 4);

        float mna = fmaxf(ma, ta);
        float mnk = fmaxf(mk, tk);
        float sca = __expf(ma - mna);
        float sck = __expf(mk - mnk);
        float pa  = __expf(ta - mna);
        float pk  = __expf(tk - mnk);
        da = fmaf(da, sca, pa);
        dk = fmaf(dk, sck, pk);
        #pragma unroll
        for (int j = 0; j < 4; ++j) {
            aca[j].x = fmaf(aca[j].x, sca, pa * xa[j].x);
            aca[j].y = fmaf(aca[j].y, sca, pa * xa[j].y);
            aca[j].z = fmaf(aca[j].z, sca, pa * xa[j].z);
            aca[j].w = fmaf(aca[j].w, sca, pa * xa[j].w);
            ack[j].x = fmaf(ack[j].x, sck, pk * xk[j].x);
            ack[j].y = fmaf(ack[j].y, sck, pk * xk[j].y);
            ack[j].z = fmaf(ack[j].z, sck, pk * xk[j].z);
            ack[j].w = fmaf(ack[j].w, sck, pk * xk[j].w);
        }
        ma = mna;
        mk = mnk;
    }

    float inva = 0.25f / da, invk = 0.25f / dk;
    float* aa = (float*)aca;
    float* ak = (float*)ack;
    #pragma unroll
    for (int i = 0; i < 16; ++i) {
        float va = aa[i] * inva;
        float vk = ak[i] * invk;
        va += __shfl_xor_sync(0xffffffffu, va, 8);
        vk += __shfl_xor_sync(0xffffffffu, vk, 8);
        va += __shfl_xor_sync(0xffffffffu, va, 16);
        vk += __shfl_xor_sync(0xffffffffu, vk, 16);
        aa[i] = va;
        ak[i] = vk;
    }

    int fb = l8 * 4;
    const float4* hrp = (const float4*)(hres + (size_t)n * 128) + fb;
    float4 hr4[4];
    #pragma unroll
    for (int j = 0; j < 4; ++j) hr4[j] = hrp[j];

    // ---- actor epilogue ----
    {
        const float4* gbp = (const float4*)gb_a + fb;
        float4 v4[4];
        float s1 = 0.f, s2 = 0.f;
        #pragma unroll
        for (int j = 0; j < 4; ++j) {
            float4 gb = gbp[j];
            v4[j].x = aca[j].x + gb.x + hr4[j].x;
            v4[j].y = aca[j].y + gb.y + hr4[j].y;
            v4[j].z = aca[j].z + gb.z + hr4[j].z;
            v4[j].w = aca[j].w + gb.w + hr4[j].w;
            s1 += v4[j].x + v4[j].y + v4[j].z + v4[j].w;
            s2 += v4[j].x * v4[j].x + v4[j].y * v4[j].y + v4[j].z * v4[j].z + v4[j].w * v4[j].w;
        }
        s1 += __shfl_xor_sync(0xffffffffu, s1, 1);
        s2 += __shfl_xor_sync(0xffffffffu, s2, 1);
        s1 += __shfl_xor_sync(0xffffffffu, s1, 2);
        s2 += __shfl_xor_sync(0xffffffffu, s2, 2);
        s1 += __shfl_xor_sync(0xffffffffu, s1, 4);
        s2 += __shfl_xor_sync(0xffffffffu, s2, 4);
        float mean = s1 * (1.f / 128.f);
        float var  = s2 * (1.f / 128.f) - mean * mean;
        float rstd = rsqrtf(var + 1e-5f);
        const float4* gp = (const float4*)lng_a + fb;
        const float4* bp = (const float4*)lnb_a + fb;
        const float4* wp = (const float4*)hw_a + fb;
        float pp = 0.f;
        #pragma unroll
        for (int j = 0; j < 4; ++j) {
            float4 gg = gp[j], bb = bp[j], w4 = wp[j];
            float yx = fmaxf((v4[j].x - mean) * rstd * gg.x + bb.x, 0.f);
            float yy = fmaxf((v4[j].y - mean) * rstd * gg.y + bb.y, 0.f);
            float yz = fmaxf((v4[j].z - mean) * rstd * gg.z + bb.z, 0.f);
            float yw = fmaxf((v4[j].w - mean) * rstd * gg.w + bb.w, 0.f);
            pp = fmaf(yx, w4.x, pp);
            pp = fmaf(yy, w4.y, pp);
            pp = fmaf(yz, w4.z, pp);
            pp = fmaf(yw, w4.w, pp);
        }
        pp += __shfl_xor_sync(0xffffffffu, pp, 1);
        pp += __shfl_xor_sync(0xffffffffu, pp, 2);
        pp += __shfl_xor_sync(0xffffffffu, pp, 4);
        if (lane == 0) out_a[n] = pp + hb_a[0];
    }
    // ---- critic epilogue ----
    {
        const float4* gbp = (const float4*)gb_k + fb;
        float4 v4[4];
        float s1 = 0.f, s2 = 0.f;
        #pragma unroll
        for (int j = 0; j < 4; ++j) {
            float4 gb = gbp[j];
            v4[j].x = ack[j].x + gb.x + hr4[j].x;
            v4[j].y = ack[j].y + gb.y + hr4[j].y;
            v4[j].z = ack[j].z + gb.z + hr4[j].z;
            v4[j].w = ack[j].w + gb.w + hr4[j].w;
            s1 += v4[j].x + v4[j].y + v4[j].z + v4[j].w;
            s2 += v4[j].x * v4[j].x + v4[j].y * v4[j].y + v4[j].z * v4[j].z + v4[j].w * v4[j].w;
        }
        s1 += __shfl_xor_sync(0xffffffffu, s1, 1);
        s2 += __shfl_xor_sync(0xffffffffu, s2, 1);
        s1 += __shfl_xor_sync(0xffffffffu, s1, 2);
        s2 += __shfl_xor_sync(0xffffffffu, s2, 2);
        s1 += __shfl_xor_sync(0xffffffffu, s1, 4);
        s2 += __shfl_xor_sync(0xffffffffu, s2, 4);
        float mean = s1 * (1.f / 128.f);
        float var  = s2 * (1.f / 128.f) - mean * mean;
        float rstd = rsqrtf(var + 1e-5f);
        const float4* gp = (const float4*)lng_k + fb;
        const float4* bp = (const float4*)lnb_k + fb;
        const float4* wp = (const float4*)hw_k + fb;
        float pp = 0.f;
        #pragma unroll
        for (int j = 0; j < 4; ++j) {
            float4 gg = gp[j], bb = bp[j], w4 = wp[j];
            float yx = fmaxf((v4[j].x - mean) * rstd * gg.x + bb.x, 0.f);
            float yy = fmaxf((v4[j].y - mean) * rstd * gg.y + bb.y, 0.f);
            float yz = fmaxf((v4[j].z - mean) * rstd * gg.z + bb.z, 0.f);
            float yw = fmaxf((v4[j].w - mean) * rstd * gg.w + bb.w, 0.f);
            pp = fmaf(yx, w4.x, pp);
            pp = fmaf(yy, w4.y, pp);
            pp = fmaf(yz, w4.z, pp);
            pp = fmaf(yw, w4.w, pp);
        }
        pp += __shfl_xor_sync(0xffffffffu, pp, 1);
        pp += __shfl_xor_sync(0xffffffffu, pp, 2);
        pp += __shfl_xor_sync(0xffffffffu, pp, 4);
        if (lane == 0) out_k[n] = pp + hb_k[0];
    }
}

// ---------------- launch ----------------
extern "C" void kernel_launch(void* const* d_in, const int* in_sizes, int n_in,
                              void* d_out, int out_size) {
    const float* x     = (const float*)d_in[0];
    const int*   ei    = (const int*)d_in[1];
    const float* W_in  = (const float*)d_in[2];
    const float* b_in  = (const float*)d_in[3];
    const float* c1_Wl = (const float*)d_in[4];
    const float* c1_bl = (const float*)d_in[5];
    const float* c1_Wr = (const float*)d_in[6];
    const float* c1_br = (const float*)d_in[7];
    const float* c1_att= (const float*)d_in[8];
    const float* c1_b  = (const float*)d_in[9];
    const float* ln1_g = (const float*)d_in[10];
    const float* ln1_b = (const float*)d_in[11];
    const float* a_Wl  = (const float*)d_in[12];
    const float* a_bl  = (const float*)d_in[13];
    const float* a_Wr  = (const float*)d_in[14];
    const float* a_br  = (const float*)d_in[15];
    const float* a_att = (const float*)d_in[16];
    const float* a_b   = (const float*)d_in[17];
    const float* aln_g = (const float*)d_in[18];
    const float* aln_b = (const float*)d_in[19];
    const float* ah_W  = (const float*)d_in[20];
    const float* ah_b  = (const float*)d_in[21];
    const float* k_Wl  = (const float*)d_in[22];
    const float* k_bl  = (const float*)d_in[23];
    const float* k_Wr  = (const float*)d_in[24];
    const float* k_br  = (const float*)d_in[25];
    const float* k_att = (const float*)d_in[26];
    const float* k_b   = (const float*)d_in[27];
    const float* kln_g = (const float*)d_in[28];
    const float* kln_b = (const float*)d_in[29];
    const float* kh_W  = (const float*)d_in[30];
    const float* kh_b  = (const float*)d_in[31];

    int N = in_sizes[0] / 128;
    int E = in_sizes[1] / 2;
    float* out = (float*)d_out;

    float *h1, *h2, *biasc;
    __half *xlxr, *xlxr2;
    __nv_bfloat16 *ahi, *alo, *wthi, *wtlo;
    cudaGetSymbolAddress((void**)&h1, g_h1);
    cudaGetSymbolAddress((void**)&h2, g_h2);
    cudaGetSymbolAddress((void**)&xlxr, g_xlxr);
    cudaGetSymbolAddress((void**)&xlxr2, g_xlxr2);
    cudaGetSymbolAddress((void**)&biasc, g_biasc);
    cudaGetSymbolAddress((void**)&ahi, g_ahi);
    cudaGetSymbolAddress((void**)&alo, g_alo);
    cudaGetSymbolAddress((void**)&wthi, g_wthi);
    cudaGetSymbolAddress((void**)&wtlo, g_wtlo);

    cudaFuncSetAttribute(gemm_mma_k, cudaFuncAttributeMaxDynamicSharedMemorySize, GMM_SMEM);

    int gc = (N * 32 + 255) / 256;
    const int NOSPLIT = 1 << 30;

    conv_all_k<<<(2048 + 6 * 8192 + WT_ROWS + 255) / 256, 256>>>(          // 1
        W_in, c1_Wl, c1_Wr, a_Wl, a_Wr, k_Wl, k_Wr,
        b_in, c1_bl, c1_br, a_bl, a_br, k_bl, k_br, N);
    conv_a_k<<<gc, 256>>>(x, N * 32);                                      // 2
    gemm_mma_k<<<dim3(148, 1), 512, GMM_SMEM>>>(ahi, alo, N,               // 3: input layer
        wthi, wtlo, biasc, h1, (float*)0, NOSPLIT, 128, 1, 1, 0);
    gemm_mma_k<<<dim3(18, 8), 512, GMM_SMEM>>>(ahi, alo, N,                // 4 <- profiled
        wthi + (size_t)128 * 128, wtlo + (size_t)128 * 128, biasc + 128,
        (float*)xlxr, (float*)0, NOSPLIT, 1024, 0, 0, 1);

    count_k<<<(E + 255) / 256, 256>>>(ei + E, E);                          // 5
    scan2_k<<<1, 1024>>>(N);                                               // 6
    scatter_k<<<(E + N + 255) / 256, 256>>>(ei, ei + E, E, N);             // 7

    gat2_k<<<N, 32>>>(xlxr, h1, c1_att, c1_b, ln1_g, ln1_b, h2, N);        // 8

    gemm_mma_k<<<dim3(9, 16), 512, GMM_SMEM>>>(ahi, alo, N,                // 9
        wthi + (size_t)1152 * 128, wtlo + (size_t)1152 * 128, biasc + 1152,
        (float*)xlxr, (float*)xlxr2, 1024, 1024, 0, 0, 1);

    gatf_k<<<N, 32>>>(xlxr, xlxr2, h2,                                     // 10: fused actor+critic
                      a_att, k_att, a_b, k_b,
                      aln_g, aln_b, kln_g, kln_b,
                      ah_W, ah_b, kh_W, kh_b,
                      out, out + N, N);
}

// round 17
// speedup vs baseline: 1.3770x; 1.0305x over previous
#include <cuda_runtime.h>
#include <cuda_bf16.h>
#include <cuda_fp16.h>
#include <math_constants.h>
#include <cstdint>

// Problem constants (fixed dataset shapes)
#define NMAX 20000
#define EMAX 320000
#define ETOT (EMAX + NMAX)

// ---------------- device scratch (static allocations only) ----------------
__device__ float  g_h1[(size_t)NMAX * 128];
__device__ float  g_h2[(size_t)NMAX * 128];
__device__ __half g_xlxr[(size_t)NMAX * 1024];    // layer1 & actor: [xl(512) | xr(512)] fp16
__device__ __half g_xlxr2[(size_t)NMAX * 1024];   // critic, fp16
__device__ int    g_cnt[NMAX];
__device__ int    g_rp[NMAX + 1];
__device__ int    g_cur[NMAX];
__device__ int    g_csrc[ETOT];

// bf16 hi/lo activations
__device__ __nv_bfloat16 g_ahi[(size_t)NMAX * 128];
__device__ __nv_bfloat16 g_alo[(size_t)NMAX * 128];
// transposed bf16 hi/lo weights: rows = 128(W_in) + 6*512 = 3200, each row 128 bf16
#define WT_ROWS 3200
__device__ __nv_bfloat16 g_wthi[(size_t)WT_ROWS * 128];
__device__ __nv_bfloat16 g_wtlo[(size_t)WT_ROWS * 128];
// packed biases, index-matched to wt rows
__device__ float g_biasc[WT_ROWS];

// ---------------- CSR scan + scatter ----------------
__global__ void scan2_k(int N) {
    __shared__ int wsum[32];
    int tid = threadIdx.x;
    int lane = tid & 31, wid = tid >> 5;
    int per = (N + 1023) >> 10;
    int start = tid * per;
    int s = 0;
    for (int i = 0; i < per; ++i) {
        int idx = start + i;
        if (idx < N) s += g_cnt[idx];
    }
    int v = s;
    #pragma unroll
    for (int off = 1; off < 32; off <<= 1) {
        int t = __shfl_up_sync(0xffffffffu, v, off);
        if (lane >= off) v += t;
    }
    if (lane == 31) wsum[wid] = v;
    __syncthreads();
    if (wid == 0) {
        int w = wsum[lane];
        #pragma unroll
        for (int off = 1; off < 32; off <<= 1) {
            int t = __shfl_up_sync(0xffffffffu, w, off);
            if (lane >= off) w += t;
        }
        wsum[lane] = w;
    }
    __syncthreads();
    int excl = v - s + (wid ? wsum[wid - 1] : 0);
    int run = excl;
    for (int i = 0; i < per; ++i) {
        int idx = start + i;
        if (idx < N) {
            int c = g_cnt[idx];
            g_cur[idx] = run;
            run += c;
            g_rp[idx + 1] = run;
        }
    }
    if (tid == 0) g_rp[0] = 0;
}
__global__ void scatter_k(const int* __restrict__ srcv, const int* __restrict__ dstv,
                          int E, int N) {
    int i = blockIdx.x * blockDim.x + threadIdx.x;
    if (i < E) {
        int d = dstv[i];
        int pos = atomicAdd(&g_cur[d], 1);
        g_csrc[pos] = srcv[i];
    } else if (i < E + N) {
        int n = i - E;
        int pos = atomicAdd(&g_cur[n], 1);
        g_csrc[pos] = n;
    }
}

__device__ __forceinline__ uint32_t pack_bf2(__nv_bfloat16 a, __nv_bfloat16 b) {
    return (uint32_t)__bfloat16_as_ushort(a) | ((uint32_t)__bfloat16_as_ushort(b) << 16);
}

__global__ void init_cnt_k(int N) {
    int i = blockIdx.x * blockDim.x + threadIdx.x;
    if (i < N) g_cnt[i] = 1;   // self-loop pre-count (SOLE initializer of g_cnt)
}

// ---------------- fused prep: edge count atomics, weights conv, bias pack, x conv ----------------
// NOTE: g_cnt is initialized by init_cnt_k in a PRIOR launch; this kernel only atomically adds.
__global__ void prep_k(const float* __restrict__ w0, const float* __restrict__ w1,
                       const float* __restrict__ w2, const float* __restrict__ w3,
                       const float* __restrict__ w4, const float* __restrict__ w5,
                       const float* __restrict__ w6,
                       const float* __restrict__ b0, const float* __restrict__ b1,
                       const float* __restrict__ b2, const float* __restrict__ b3,
                       const float* __restrict__ b4, const float* __restrict__ b5,
                       const float* __restrict__ b6,
                       const int* __restrict__ dstv, int E,
                       const float* __restrict__ x, int N) {
    int i = blockIdx.x * blockDim.x + threadIdx.x;
    if (i < E) atomicAdd(&g_cnt[dstv[i]], 1);      // edge counts
    const int WTH = 2048 + 6 * 8192;   // 51200
    if (i < WTH) {
        const float* W; int cols, rowoff, n, kg;
        if (i < 2048) { W = w0; cols = 128; rowoff = 0; n = i & 127; kg = i >> 7; }
        else {
            int j = i - 2048;
            int s = j >> 13;
            int r = j & 8191;
            n = r & 511; kg = r >> 9;
            W = (s == 0) ? w1 : (s == 1) ? w2 : (s == 2) ? w3 : (s == 3) ? w4 : (s == 4) ? w5 : w6;
            cols = 512; rowoff = 128 + s * 512;
        }
        int k0 = kg * 8;
        __nv_bfloat16 h8[8], l8v[8];
        #pragma unroll
        for (int q = 0; q < 8; ++q) {
            float v = W[(size_t)(k0 + q) * cols + n];
            __nv_bfloat16 h = __float2bfloat16(v);
            h8[q] = h;
            l8v[q] = __float2bfloat16(v - __bfloat162float(h));
        }
        uint4 hv, lv;
        hv.x = pack_bf2(h8[0], h8[1]); hv.y = pack_bf2(h8[2], h8[3]);
        hv.z = pack_bf2(h8[4], h8[5]); hv.w = pack_bf2(h8[6], h8[7]);
        lv.x = pack_bf2(l8v[0], l8v[1]); lv.y = pack_bf2(l8v[2], l8v[3]);
        lv.z = pack_bf2(l8v[4], l8v[5]); lv.w = pack_bf2(l8v[6], l8v[7]);
        *(uint4*)(g_wthi + (size_t)(rowoff + n) * 128 + k0) = hv;
        *(uint4*)(g_wtlo + (size_t)(rowoff + n) * 128 + k0) = lv;
    } else if (i < WTH + WT_ROWS) {
        int j = i - WTH;
        float v;
        if (j < 128) v = b0[j];
        else {
            int s = (j - 128) >> 9, t = (j - 128) & 511;
            const float* B = (s == 0) ? b1 : (s == 1) ? b2 : (s == 2) ? b3
                           : (s == 3) ? b4 : (s == 4) ? b5 : b6;
            v = B[t];
        }
        g_biasc[j] = v;
    }
    // x -> bf16 hi/lo  (N*32 uint2 chunks)
    if (i < N * 32) {
        float4 v = ((const float4*)x)[i];
        __nv_bfloat16 hx = __float2bfloat16(v.x);
        __nv_bfloat16 hy = __float2bfloat16(v.y);
        __nv_bfloat16 hz = __float2bfloat16(v.z);
        __nv_bfloat16 hw = __float2bfloat16(v.w);
        __nv_bfloat16 lx = __float2bfloat16(v.x - __bfloat162float(hx));
        __nv_bfloat16 ly = __float2bfloat16(v.y - __bfloat162float(hy));
        __nv_bfloat16 lz = __float2bfloat16(v.z - __bfloat162float(hz));
        __nv_bfloat16 lw = __float2bfloat16(v.w - __bfloat162float(hw));
        ((uint2*)g_ahi)[i] = make_uint2(pack_bf2(hx, hy), pack_bf2(hz, hw));
        ((uint2*)g_alo)[i] = make_uint2(pack_bf2(lx, ly), pack_bf2(lz, lw));
    }
}

// ======== bf16x3 GEMM v4: persistent col tile, double-buffered A, 512 threads ========
#define TSTRIDE 272
#define TILE_B (128 * TSTRIDE)
#define GMM_SMEM (6 * TILE_B)

__device__ __forceinline__ uint32_t smem_u32(const void* p) {
    uint32_t a;
    asm("{ .reg .u64 t; cvta.to.shared.u64 t, %1; cvt.u32.u64 %0, t; }" : "=r"(a) : "l"(p));
    return a;
}

#define CP16(dst, src, sz) \
    asm volatile("cp.async.cg.shared.global [%0], [%1], 16, %2;" \
                 :: "r"(dst), "l"(src), "r"(sz) : "memory")
#define CP_COMMIT() asm volatile("cp.async.commit_group;" ::: "memory")
#define CP_WAIT0()  asm volatile("cp.async.wait_group 0;" ::: "memory")
#define CP_WAIT1()  asm volatile("cp.async.wait_group 1;" ::: "memory")

#define LDMX4(r0, r1, r2, r3, addr) \
    asm volatile("ldmatrix.sync.aligned.m8n8.x4.shared.b16 {%0,%1,%2,%3}, [%4];" \
                 : "=r"(r0), "=r"(r1), "=r"(r2), "=r"(r3) : "r"(addr))

#define MMA_BF16(c, a0, a1, a2, a3, b0, b1) \
    asm volatile("mma.sync.aligned.m16n8k16.row.col.f32.bf16.bf16.f32 " \
                 "{%0,%1,%2,%3}, {%4,%5,%6,%7}, {%8,%9}, {%0,%1,%2,%3};" \
                 : "+f"((c)[0]), "+f"((c)[1]), "+f"((c)[2]), "+f"((c)[3]) \
                 : "r"(a0), "r"(a1), "r"(a2), "r"(a3), "r"(b0), "r"(b1))

__device__ __forceinline__ void prefetch_A(uint32_t uAhi, uint32_t uAlo,
                                           const __nv_bfloat16* Ahi, const __nv_bfloat16* Alo,
                                           int row0, int M, int tid) {
    #pragma unroll
    for (int it = 0; it < 4; ++it) {
        int idx = it * 512 + tid;
        int row = idx >> 4, c = idx & 15;
        int grow = row0 + row;
        int ok = grow < M;
        int srow = ok ? grow : 0;
        uint32_t sz = ok ? 16u : 0u;
        CP16(uAhi + row * TSTRIDE + c * 16,
             (const char*)(Ahi + (size_t)srow * 128) + c * 16, sz);
        CP16(uAlo + row * TSTRIDE + c * 16,
             (const char*)(Alo + (size_t)srow * 128) + c * 16, sz);
    }
}

__global__ void __launch_bounds__(512, 1)
gemm_mma_k(const __nv_bfloat16* __restrict__ Ahi, const __nv_bfloat16* __restrict__ Alo, int M,
           const __nv_bfloat16* __restrict__ Bhi, const __nv_bfloat16* __restrict__ Blo,
           const float* __restrict__ bias,
           float* __restrict__ out, float* __restrict__ out2, int split,
           int ldo, int do_relu, int conv_out, int store_half) {
    extern __shared__ char sm[];
    char* sBhi = sm;
    char* sBlo = sm + TILE_B;
    char* sA[2][2];
    sA[0][0] = sm + 2 * TILE_B;
    sA[0][1] = sm + 3 * TILE_B;
    sA[1][0] = sm + 4 * TILE_B;
    sA[1][1] = sm + 5 * TILE_B;

    int tid = threadIdx.x;
    int wc0 = blockIdx.y * 128;
    int oc  = wc0;
    if (oc >= split) { out = out2; oc -= split; }

    uint32_t uBhi = smem_u32(sBhi), uBlo = smem_u32(sBlo);
    uint32_t uA[2][2];
    #pragma unroll
    for (int s = 0; s < 2; ++s) { uA[s][0] = smem_u32(sA[s][0]); uA[s][1] = smem_u32(sA[s][1]); }

    #pragma unroll
    for (int it = 0; it < 4; ++it) {
        int idx = it * 512 + tid;
        int row = idx >> 4, c = idx & 15;
        CP16(uBhi + row * TSTRIDE + c * 16,
             (const char*)(Bhi + (size_t)(wc0 + row) * 128) + c * 16, 16u);
        CP16(uBlo + row * TSTRIDE + c * 16,
             (const char*)(Blo + (size_t)(wc0 + row) * 128) + c * 16, 16u);
    }
    int nrt = (M + 127) >> 7;
    int stride = gridDim.x;
    int r0 = blockIdx.x;
    if (r0 < nrt)
        prefetch_A(uA[0][0], uA[0][1], Ahi, Alo, r0 * 128, M, tid);
    CP_COMMIT();

    int wid = tid >> 5;
    int lane = tid & 31;
    int m0 = (wid & 3) * 32;
    int n0 = (wid >> 2) * 32;

    int gq = lane >> 3, l8 = lane & 7;
    int fr_row = (gq & 1) * 8 + l8;
    int fr_col = (gq >> 1) * 16;

    uint32_t aoff[2], boff[2];
    #pragma unroll
    for (int mt = 0; mt < 2; ++mt)
        aoff[mt] = (uint32_t)((m0 + mt * 16 + fr_row) * TSTRIDE + fr_col);
    #pragma unroll
    for (int nt2 = 0; nt2 < 2; ++nt2)
        boff[nt2] = (uint32_t)((n0 + nt2 * 16 + fr_row) * TSTRIDE + fr_col);

    int qr = lane >> 2;
    int qc = (lane & 3) * 2;
    float2 bv[4];
    #pragma unroll
    for (int nt = 0; nt < 4; ++nt)
        bv[nt] = *(const float2*)(bias + wc0 + n0 + nt * 8 + qc);

    int buf = 0;
    for (int r = r0; r < nrt; r += stride) {
        int rn = r + stride;
        if (rn < nrt)
            prefetch_A(uA[buf ^ 1][0], uA[buf ^ 1][1], Ahi, Alo, rn * 128, M, tid);
        CP_COMMIT();
        if (rn < nrt) CP_WAIT1(); else CP_WAIT0();
        __syncthreads();

        uint32_t uAhi = uA[buf][0], uAlo = uA[buf][1];

        float c[2][4][4];
        #pragma unroll
        for (int mt = 0; mt < 2; ++mt)
            #pragma unroll
            for (int nt = 0; nt < 4; ++nt)
                #pragma unroll
                for (int q = 0; q < 4; ++q) c[mt][nt][q] = 0.f;

        #pragma unroll
        for (int kk = 0; kk < 8; ++kk) {
            uint32_t ah[2][4], al2[2][4];
            #pragma unroll
            for (int mt = 0; mt < 2; ++mt) {
                LDMX4(ah[mt][0], ah[mt][1], ah[mt][2], ah[mt][3], uAhi + aoff[mt] + kk * 32);
                LDMX4(al2[mt][0], al2[mt][1], al2[mt][2], al2[mt][3], uAlo + aoff[mt] + kk * 32);
            }
            uint32_t bh[2][4], bl[2][4];
            #pragma unroll
            for (int nt2 = 0; nt2 < 2; ++nt2) {
                LDMX4(bh[nt2][0], bh[nt2][1], bh[nt2][2], bh[nt2][3], uBhi + boff[nt2] + kk * 32);
                LDMX4(bl[nt2][0], bl[nt2][1], bl[nt2][2], bl[nt2][3], uBlo + boff[nt2] + kk * 32);
            }
            #pragma unroll
            for (int mt = 0; mt < 2; ++mt)
                #pragma unroll
                for (int nt = 0; nt < 4; ++nt) {
                    int nt2 = nt >> 1, odd = nt & 1;
                    MMA_BF16(c[mt][nt], ah[mt][0], ah[mt][1], ah[mt][2], ah[mt][3],
                             bh[nt2][odd], bh[nt2][2 + odd]);
                    MMA_BF16(c[mt][nt], ah[mt][0], ah[mt][1], ah[mt][2], ah[mt][3],
                             bl[nt2][odd], bl[nt2][2 + odd]);
                    MMA_BF16(c[mt][nt], al2[mt][0], al2[mt][1], al2[mt][2], al2[mt][3],
                             bh[nt2][odd], bh[nt2][2 + odd]);
                }
        }

        int row0 = r * 128;
        #pragma unroll
        for (int mt = 0; mt < 2; ++mt) {
            int r_lo = row0 + m0 + mt * 16 + qr;
            #pragma unroll
            for (int nt = 0; nt < 4; ++nt) {
                int colb = n0 + nt * 8 + qc;
                float2 v0 = make_float2(c[mt][nt][0] + bv[nt].x, c[mt][nt][1] + bv[nt].y);
                float2 v1 = make_float2(c[mt][nt][2] + bv[nt].x, c[mt][nt][3] + bv[nt].y);
                if (do_relu) {
                    v0.x = fmaxf(v0.x, 0.f); v0.y = fmaxf(v0.y, 0.f);
                    v1.x = fmaxf(v1.x, 0.f); v1.y = fmaxf(v1.y, 0.f);
                }
                #pragma unroll
                for (int half = 0; half < 2; ++half) {
                    int rr = r_lo + half * 8;
                    float2 vv = half ? v1 : v0;
                    if (rr < M) {
                        if (store_half) {
                            __half2 hv = __floats2half2_rn(vv.x, vv.y);
                            *(__half2*)((__half*)out + (size_t)rr * ldo + oc + colb) = hv;
                        } else {
                            *(float2*)(out + (size_t)rr * ldo + oc + colb) = vv;
                            if (conv_out) {
                                __nv_bfloat16 hx = __float2bfloat16(vv.x);
                                __nv_bfloat16 hy = __float2bfloat16(vv.y);
                                __nv_bfloat16 lx = __float2bfloat16(vv.x - __bfloat162float(hx));
                                __nv_bfloat16 ly = __float2bfloat16(vv.y - __bfloat162float(hy));
                                size_t ai = (size_t)rr * 128 + oc + colb;
                                *(uint32_t*)(g_ahi + ai) = pack_bf2(hx, hy);
                                *(uint32_t*)(g_alo + ai) = pack_bf2(lx, ly);
                            }
                        }
                    }
                }
            }
        }
        __syncthreads();
        buf ^= 1;
    }
}

// ---------------- fp16 feature load: 16 halfs -> 4 float4 ----------------
__device__ __forceinline__ void ldh16(const __half* base, int cbh, float4 x[4]) {
    const uint4* p = (const uint4*)base;
    uint4 v0 = p[cbh];
    uint4 v1 = p[cbh + 1];
    float2 a;
    a = __half22float2(*(const __half2*)&v0.x); x[0].x = a.x; x[0].y = a.y;
    a = __half22float2(*(const __half2*)&v0.y); x[0].z = a.x; x[0].w = a.y;
    a = __half22float2(*(const __half2*)&v0.z); x[1].x = a.x; x[1].y = a.y;
    a = __half22float2(*(const __half2*)&v0.w); x[1].z = a.x; x[1].w = a.y;
    a = __half22float2(*(const __half2*)&v1.x); x[2].x = a.x; x[2].y = a.y;
    a = __half22float2(*(const __half2*)&v1.y); x[2].z = a.x; x[2].w = a.y;
    a = __half22float2(*(const __half2*)&v1.z); x[3].x = a.x; x[3].y = a.y;
    a = __half22float2(*(const __half2*)&v1.w); x[3].z = a.x; x[3].w = a.y;
}

// ===== GATv2 layer-1: one warp per block, fp16 feature gather, 2-edge unroll =====
#define LRD(t, x4, r4, a4) do {                                        \
    float ex = (x4).x + (r4).x; ex = fmaxf(ex, 0.2f * ex); t = fmaf(ex, (a4).x, t); \
    float ey = (x4).y + (r4).y; ey = fmaxf(ey, 0.2f * ey); t = fmaf(ey, (a4).y, t); \
    float ez = (x4).z + (r4).z; ez = fmaxf(ez, 0.2f * ez); t = fmaf(ez, (a4).z, t); \
    float ew = (x4).w + (r4).w; ew = fmaxf(ew, 0.2f * ew); t = fmaf(ew, (a4).w, t); \
} while (0)

__global__ void __launch_bounds__(32)
gat2_k(const __half* __restrict__ xlxr,
       const float* __restrict__ hres,
       const float* __restrict__ att,
       const float* __restrict__ gatb,
       const float* __restrict__ lng,
       const float* __restrict__ lnb,
       float* __restrict__ outh,
       int N) {
    int n    = blockIdx.x;
    int lane = threadIdx.x;
    if (n >= N) return;
    int g  = lane >> 3;
    int l8 = lane & 7;
    int cb = g * 32 + l8 * 4;
    int cbh = cb >> 1;

    float4 atv[4], xrv[4];
    const float4* ap = (const float4*)att + cb;
    #pragma unroll
    for (int j = 0; j < 4; ++j) atv[j] = ap[j];
    ldh16(xlxr + (size_t)n * 1024 + 512, cbh, xrv);

    float m = -CUDART_INF_F, d = 0.f;
    float4 acc[4];
    #pragma unroll
    for (int j = 0; j < 4; ++j) acc[j] = make_float4(0.f, 0.f, 0.f, 0.f);

    int e = g_rp[n], end = g_rp[n + 1];
    for (; e + 2 <= end; e += 2) {
        int s0 = g_csrc[e];
        int s1 = g_csrc[e + 1];
        float4 x0[4], x1[4];
        ldh16(xlxr + (size_t)s0 * 1024, cbh, x0);
        ldh16(xlxr + (size_t)s1 * 1024, cbh, x1);

        float t0 = 0.f, t1 = 0.f;
        #pragma unroll
        for (int j = 0; j < 4; ++j) { LRD(t0, x0[j], xrv[j], atv[j]); LRD(t1, x1[j], xrv[j], atv[j]); }
        t0 += __shfl_xor_sync(0xffffffffu, t0, 1);
        t1 += __shfl_xor_sync(0xffffffffu, t1, 1);
        t0 += __shfl_xor_sync(0xffffffffu, t0, 2);
        t1 += __shfl_xor_sync(0xffffffffu, t1, 2);
        t0 += __shfl_xor_sync(0xffffffffu, t0, 4);
        t1 += __shfl_xor_sync(0xffffffffu, t1, 4);

        float mn = fmaxf(m, fmaxf(t0, t1));
        float sc = __expf(m - mn);
        float p0 = __expf(t0 - mn);
        float p1 = __expf(t1 - mn);
        d = fmaf(d, sc, p0 + p1);
        #pragma unroll
        for (int j = 0; j < 4; ++j) {
            acc[j].x = fmaf(acc[j].x, sc, fmaf(p0, x0[j].x, p1 * x1[j].x));
            acc[j].y = fmaf(acc[j].y, sc, fmaf(p0, x0[j].y, p1 * x1[j].y));
            acc[j].z = fmaf(acc[j].z, sc, fmaf(p0, x0[j].z, p1 * x1[j].z));
            acc[j].w = fmaf(acc[j].w, sc, fmaf(p0, x0[j].w, p1 * x1[j].w));
        }
        m = mn;
    }
    if (e < end) {
        int s0 = g_csrc[e];
        float4 x0[4];
        ldh16(xlxr + (size_t)s0 * 1024, cbh, x0);
        float t0 = 0.f;
        #pragma unroll
        for (int j = 0; j < 4; ++j) LRD(t0, x0[j], xrv[j], atv[j]);
        t0 += __shfl_xor_sync(0xffffffffu, t0, 1);
        t0 += __shfl_xor_sync(0xffffffffu, t0, 2);
        t0 += __shfl_xor_sync(0xffffffffu, t0, 4);
        float mn = fmaxf(m, t0);
        float sc = __expf(m - mn);
        float p0 = __expf(t0 - mn);
        d = fmaf(d, sc, p0);
        #pragma unroll
        for (int j = 0; j < 4; ++j) {
            acc[j].x = fmaf(acc[j].x, sc, p0 * x0[j].x);
            acc[j].y = fmaf(acc[j].y, sc, p0 * x0[j].y);
            acc[j].z = fmaf(acc[j].z, sc, p0 * x0[j].z);
            acc[j].w = fmaf(acc[j].w, sc, p0 * x0[j].w);
        }
        m = mn;
    }

    float inv = 0.25f / d;
    float* a = (float*)acc;
    #pragma unroll
    for (int i = 0; i < 16; ++i) {
        float v = a[i] * inv;
        v += __shfl_xor_sync(0xffffffffu, v, 8);
        v += __shfl_xor_sync(0xffffffffu, v, 16);
        a[i] = v;
    }

    int fb = l8 * 4;
    const float4* gbp = (const float4*)gatb + fb;
    const float4* hrp = (const float4*)(hres + (size_t)n * 128) + fb;
    float4 v4[4];
    float s1 = 0.f, s2 = 0.f;
    #pragma unroll
    for (int j = 0; j < 4; ++j) {
        float4 gb = gbp[j], hr = hrp[j];
        v4[j].x = acc[j].x + gb.x + hr.x;
        v4[j].y = acc[j].y + gb.y + hr.y;
        v4[j].z = acc[j].z + gb.z + hr.z;
        v4[j].w = acc[j].w + gb.w + hr.w;
        s1 += v4[j].x + v4[j].y + v4[j].z + v4[j].w;
        s2 += v4[j].x * v4[j].x + v4[j].y * v4[j].y + v4[j].z * v4[j].z + v4[j].w * v4[j].w;
    }
    s1 += __shfl_xor_sync(0xffffffffu, s1, 1);
    s2 += __shfl_xor_sync(0xffffffffu, s2, 1);
    s1 += __shfl_xor_sync(0xffffffffu, s1, 2);
    s2 += __shfl_xor_sync(0xffffffffu, s2, 2);
    s1 += __shfl_xor_sync(0xffffffffu, s1, 4);
    s2 += __shfl_xor_sync(0xffffffffu, s2, 4);
    float mean = s1 * (1.f / 128.f);
    float var  = s2 * (1.f / 128.f) - mean * mean;
    float rstd = rsqrtf(var + 1e-5f);

    const float4* gp = (const float4*)lng + fb;
    const float4* bp = (const float4*)lnb + fb;
    #pragma unroll
    for (int j = 0; j < 4; ++j) {
        float4 gg = gp[j], bb = bp[j];
        float4 y4;
        y4.x = fmaxf((v4[j].x - mean) * rstd * gg.x + bb.x, 0.f);
        y4.y = fmaxf((v4[j].y - mean) * rstd * gg.y + bb.y, 0.f);
        y4.z = fmaxf((v4[j].z - mean) * rstd * gg.z + bb.z, 0.f);
        y4.w = fmaxf((v4[j].w - mean) * rstd * gg.w + bb.w, 0.f);
        if (g == 0) {
            ((float4*)outh)[(size_t)n * 32 + fb + j] = y4;
            __nv_bfloat16 hx = __float2bfloat16(y4.x);
            __nv_bfloat16 hy = __float2bfloat16(y4.y);
            __nv_bfloat16 hz = __float2bfloat16(y4.z);
            __nv_bfloat16 hw = __float2bfloat16(y4.w);
            __nv_bfloat16 lx = __float2bfloat16(y4.x - __bfloat162float(hx));
            __nv_bfloat16 ly = __float2bfloat16(y4.y - __bfloat162float(hy));
            __nv_bfloat16 lz = __float2bfloat16(y4.z - __bfloat162float(hz));
            __nv_bfloat16 lw = __float2bfloat16(y4.w - __bfloat162float(hw));
            size_t ai = (size_t)n * 32 + fb + j;
            ((uint2*)g_ahi)[ai] = make_uint2(pack_bf2(hx, hy), pack_bf2(hz, hw));
            ((uint2*)g_alo)[ai] = make_uint2(pack_bf2(lx, ly), pack_bf2(lz, lw));
        }
    }
}

// ===== Fused actor+critic GAT: one warp/node, fp16, 2-edge unroll =====
__global__ void __launch_bounds__(32)
gatf_k(const __half* __restrict__ xla,
       const __half* __restrict__ xlk,
       const float* __restrict__ hres,
       const float* __restrict__ att_a, const float* __restrict__ att_k,
       const float* __restrict__ gb_a,  const float* __restrict__ gb_k,
       const float* __restrict__ lng_a, const float* __restrict__ lnb_a,
       const float* __restrict__ lng_k, const float* __restrict__ lnb_k,
       const float* __restrict__ hw_a,  const float* __restrict__ hb_a,
       const float* __restrict__ hw_k,  const float* __restrict__ hb_k,
       float* __restrict__ out_a, float* __restrict__ out_k,
       int N) {
    int n    = blockIdx.x;
    int lane = threadIdx.x;
    if (n >= N) return;
    int g  = lane >> 3;
    int l8 = lane & 7;
    int cb = g * 32 + l8 * 4;
    int cbh = cb >> 1;

    float4 ata[4], xra[4], atk[4], xrk[4];
    {
        const float4* apa = (const float4*)att_a + cb;
        const float4* apk = (const float4*)att_k + cb;
        #pragma unroll
        for (int j = 0; j < 4; ++j) { ata[j] = apa[j]; atk[j] = apk[j]; }
        ldh16(xla + (size_t)n * 1024 + 512, cbh, xra);
        ldh16(xlk + (size_t)n * 1024 + 512, cbh, xrk);
    }

    float ma = -CUDART_INF_F, da = 0.f;
    float mk = -CUDART_INF_F, dk = 0.f;
    float4 aca[4], ack[4];
    #pragma unroll
    for (int j = 0; j < 4; ++j) {
        aca[j] = make_float4(0.f, 0.f, 0.f, 0.f);
        ack[j] = make_float4(0.f, 0.f, 0.f, 0.f);
    }

    int e = g_rp[n], end = g_rp[n + 1];
    for (; e + 2 <= end; e += 2) {
        int s0 = g_csrc[e];
        int s1 = g_csrc[e + 1];
        float4 xa0[4], xk0[4], xa1[4], xk1[4];
        ldh16(xla + (size_t)s0 * 1024, cbh, xa0);
        ldh16(xla + (size_t)s1 * 1024, cbh, xa1);
        ldh16(xlk + (size_t)s0 * 1024, cbh, xk0);
        ldh16(xlk + (size_t)s1 * 1024, cbh, xk1);

        float ta0 = 0.f, ta1 = 0.f, tk0 = 0.f, tk1 = 0.f;
        #pragma unroll
        for (int j = 0; j < 4; ++j) {
            LRD(ta0, xa0[j], xra[j], ata[j]);
            LRD(ta1, xa1[j], xra[j], ata[j]);
            LRD(tk0, xk0[j], xrk[j], atk[j]);
            LRD(tk1, xk1[j], xrk[j], atk[j]);
        }
        #pragma unroll
        for (int off = 1; off <= 4; off <<= 1) {
            ta0 += __shfl_xor_sync(0xffffffffu, ta0, off);
            ta1 += __shfl_xor_sync(0xffffffffu, ta1, off);
            tk0 += __shfl_xor_sync(0xffffffffu, tk0, off);
            tk1 += __shfl_xor_sync(0xffffffffu, tk1, off);
        }

        float mna = fmaxf(ma, fmaxf(ta0, ta1));
        float mnk = fmaxf(mk, fmaxf(tk0, tk1));
        float sca = __expf(ma - mna);
        float sck = __expf(mk - mnk);
        float pa0 = __expf(ta0 - mna);
        float pa1 = __expf(ta1 - mna);
        float pk0 = __expf(tk0 - mnk);
        float pk1 = __expf(tk1 - mnk);
        da = fmaf(da, sca, pa0 + pa1);
        dk = fmaf(dk, sck, pk0 + pk1);
        #pragma unroll
        for (int j = 0; j < 4; ++j) {
            aca[j].x = fmaf(aca[j].x, sca, fmaf(pa0, xa0[j].x, pa1 * xa1[j].x));
            aca[j].y = fmaf(aca[j].y, sca, fmaf(pa0, xa0[j].y, pa1 * xa1[j].y));
            aca[j].z = fmaf(aca[j].z, sca, fmaf(pa0, xa0[j].z, pa1 * xa1[j].z));
            aca[j].w = fmaf(aca[j].w, sca, fmaf(pa0, xa0[j].w, pa1 * xa1[j].w));
            ack[j].x = fmaf(ack[j].x, sck, fmaf(pk0, xk0[j].x, pk1 * xk1[j].x));
            ack[j].y = fmaf(ack[j].y, sck, fmaf(pk0, xk0[j].y, pk1 * xk1[j].y));
            ack[j].z = fmaf(ack[j].z, sck, fmaf(pk0, xk0[j].z, pk1 * xk1[j].z));
            ack[j].w = fmaf(ack[j].w, sck, fmaf(pk0, xk0[j].w, pk1 * xk1[j].w));
        }
        ma = mna;
        mk = mnk;
    }
    if (e < end) {
        int s0 = g_csrc[e];
        float4 xa[4], xk[4];
        ldh16(xla + (size_t)s0 * 1024, cbh, xa);
        ldh16(xlk + (size_t)s0 * 1024, cbh, xk);

        float ta = 0.f, tk = 0.f;
        #pragma unroll
        for (int j = 0; j < 4; ++j) { LRD(ta, xa[j], xra[j], ata[j]); LRD(tk, xk[j], xrk[j], atk[j]); }
        #pragma unroll
        for (int off = 1; off <= 4; off <<= 1) {
            ta += __shfl_xor_sync(0xffffffffu, ta, off);
            tk += __shfl_xor_sync(0xffffffffu, tk, off);
        }
        float mna = fmaxf(ma, ta);
        float mnk = fmaxf(mk, tk);
        float sca = __expf(ma - mna);
        float sck = __expf(mk - mnk);
        float pa  = __expf(ta - mna);
        float pk  = __expf(tk - mnk);
        da = fmaf(da, sca, pa);
        dk = fmaf(dk, sck, pk);
        #pragma unroll
        for (int j = 0; j < 4; ++j) {
            aca[j].x = fmaf(aca[j].x, sca, pa * xa[j].x);
            aca[j].y = fmaf(aca[j].y, sca, pa * xa[j].y);
            aca[j].z = fmaf(aca[j].z, sca, pa * xa[j].z);
            aca[j].w = fmaf(aca[j].w, sca, pa * xa[j].w);
            ack[j].x = fmaf(ack[j].x, sck, pk * xk[j].x);
            ack[j].y = fmaf(ack[j].y, sck, pk * xk[j].y);
            ack[j].z = fmaf(ack[j].z, sck, pk * xk[j].z);
            ack[j].w = fmaf(ack[j].w, sck, pk * xk[j].w);
        }
        ma = mna;
        mk = mnk;
    }

    float inva = 0.25f / da, invk = 0.25f / dk;
    float* aa = (float*)aca;
    float* ak = (float*)ack;
    #pragma unroll
    for (int i = 0; i < 16; ++i) {
        float va = aa[i] * inva;
        float vk = ak[i] * invk;
        va += __shfl_xor_sync(0xffffffffu, va, 8);
        vk += __shfl_xor_sync(0xffffffffu, vk, 8);
        va += __shfl_xor_sync(0xffffffffu, va, 16);
        vk += __shfl_xor_sync(0xffffffffu, vk, 16);
        aa[i] = va;
        ak[i] = vk;
    }

    int fb = l8 * 4;
    const float4* hrp = (const float4*)(hres + (size_t)n * 128) + fb;
    float4 hr4[4];
    #pragma unroll
    for (int j = 0; j < 4; ++j) hr4[j] = hrp[j];

    // ---- actor epilogue ----
    {
        const float4* gbp = (const float4*)gb_a + fb;
        float4 v4[4];
        float s1 = 0.f, s2 = 0.f;
        #pragma unroll
        for (int j = 0; j < 4; ++j) {
            float4 gb = gbp[j];
            v4[j].x = aca[j].x + gb.x + hr4[j].x;
            v4[j].y = aca[j].y + gb.y + hr4[j].y;
            v4[j].z = aca[j].z + gb.z + hr4[j].z;
            v4[j].w = aca[j].w + gb.w + hr4[j].w;
            s1 += v4[j].x + v4[j].y + v4[j].z + v4[j].w;
            s2 += v4[j].x * v4[j].x + v4[j].y * v4[j].y + v4[j].z * v4[j].z + v4[j].w * v4[j].w;
        }
        s1 += __shfl_xor_sync(0xffffffffu, s1, 1);
        s2 += __shfl_xor_sync(0xffffffffu, s2, 1);
        s1 += __shfl_xor_sync(0xffffffffu, s1, 2);
        s2 += __shfl_xor_sync(0xffffffffu, s2, 2);
        s1 += __shfl_xor_sync(0xffffffffu, s1, 4);
        s2 += __shfl_xor_sync(0xffffffffu, s2, 4);
        float mean = s1 * (1.f / 128.f);
        float var  = s2 * (1.f / 128.f) - mean * mean;
        float rstd = rsqrtf(var + 1e-5f);
        const float4* gp = (const float4*)lng_a + fb;
        const float4* bp = (const float4*)lnb_a + fb;
        const float4* wp = (const float4*)hw_a + fb;
        float pp = 0.f;
        #pragma unroll
        for (int j = 0; j < 4; ++j) {
            float4 gg = gp[j], bb = bp[j], w4 = wp[j];
            float yx = fmaxf((v4[j].x - mean) * rstd * gg.x + bb.x, 0.f);
            float yy = fmaxf((v4[j].y - mean) * rstd * gg.y + bb.y, 0.f);
            float yz = fmaxf((v4[j].z - mean) * rstd * gg.z + bb.z, 0.f);
            float yw = fmaxf((v4[j].w - mean) * rstd * gg.w + bb.w, 0.f);
            pp = fmaf(yx, w4.x, pp);
            pp = fmaf(yy, w4.y, pp);
            pp = fmaf(yz, w4.z, pp);
            pp = fmaf(yw, w4.w, pp);
        }
        pp += __shfl_xor_sync(0xffffffffu, pp, 1);
        pp += __shfl_xor_sync(0xffffffffu, pp, 2);
        pp += __shfl_xor_sync(0xffffffffu, pp, 4);
        if (lane == 0) out_a[n] = pp + hb_a[0];
    }
    // ---- critic epilogue ----
    {
        const float4* gbp = (const float4*)gb_k + fb;
        float4 v4[4];
        float s1 = 0.f, s2 = 0.f;
        #pragma unroll
        for (int j = 0; j < 4; ++j) {
            float4 gb = gbp[j];
            v4[j].x = ack[j].x + gb.x + hr4[j].x;
            v4[j].y = ack[j].y + gb.y + hr4[j].y;
            v4[j].z = ack[j].z + gb.z + hr4[j].z;
            v4[j].w = ack[j].w + gb.w + hr4[j].w;
            s1 += v4[j].x + v4[j].y + v4[j].z + v4[j].w;
            s2 += v4[j].x * v4[j].x + v4[j].y * v4[j].y + v4[j].z * v4[j].z + v4[j].w * v4[j].w;
        }
        s1 += __shfl_xor_sync(0xffffffffu, s1, 1);
        s2 += __shfl_xor_sync(0xffffffffu, s2, 1);
        s1 += __shfl_xor_sync(0xffffffffu, s1, 2);
        s2 += __shfl_xor_sync(0xffffffffu, s2, 2);
        s1 += __shfl_xor_sync(0xffffffffu, s1, 4);
        s2 += __shfl_xor_sync(0xffffffffu, s2, 4);
        float mean = s1 * (1.f / 128.f);
        float var  = s2 * (1.f / 128.f) - mean * mean;
        float rstd = rsqrtf(var + 1e-5f);
        const float4* gp = (const float4*)lng_k + fb;
        const float4* bp = (const float4*)lnb_k + fb;
        const float4* wp = (const float4*)hw_k + fb;
        float pp = 0.f;
        #pragma unroll
        for (int j = 0; j < 4; ++j) {
            float4 gg = gp[j], bb = bp[j], w4 = wp[j];
            float yx = fmaxf((v4[j].x - mean) * rstd * gg.x + bb.x, 0.f);
            float yy = fmaxf((v4[j].y - mean) * rstd * gg.y + bb.y, 0.f);
            float yz = fmaxf((v4[j].z - mean) * rstd * gg.z + bb.z, 0.f);
            float yw = fmaxf((v4[j].w - mean) * rstd * gg.w + bb.w, 0.f);
            pp = fmaf(yx, w4.x, pp);
            pp = fmaf(yy, w4.y, pp);
            pp = fmaf(yz, w4.z, pp);
            pp = fmaf(yw, w4.w, pp);
        }
        pp += __shfl_xor_sync(0xffffffffu, pp, 1);
        pp += __shfl_xor_sync(0xffffffffu, pp, 2);
        pp += __shfl_xor_sync(0xffffffffu, pp, 4);
        if (lane == 0) out_k[n] = pp + hb_k[0];
    }
}

// ---------------- launch ----------------
extern "C" void kernel_launch(void* const* d_in, const int* in_sizes, int n_in,
                              void* d_out, int out_size) {
    const float* x     = (const float*)d_in[0];
    const int*   ei    = (const int*)d_in[1];
    const float* W_in  = (const float*)d_in[2];
    const float* b_in  = (const float*)d_in[3];
    const float* c1_Wl = (const float*)d_in[4];
    const float* c1_bl = (const float*)d_in[5];
    const float* c1_Wr = (const float*)d_in[6];
    const float* c1_br = (const float*)d_in[7];
    const float* c1_att= (const float*)d_in[8];
    const float* c1_b  = (const float*)d_in[9];
    const float* ln1_g = (const float*)d_in[10];
    const float* ln1_b = (const float*)d_in[11];
    const float* a_Wl  = (const float*)d_in[12];
    const float* a_bl  = (const float*)d_in[13];
    const float* a_Wr  = (const float*)d_in[14];
    const float* a_br  = (const float*)d_in[15];
    const float* a_att = (const float*)d_in[16];
    const float* a_b   = (const float*)d_in[17];
    const float* aln_g = (const float*)d_in[18];
    const float* aln_b = (const float*)d_in[19];
    const float* ah_W  = (const float*)d_in[20];
    const float* ah_b  = (const float*)d_in[21];
    const float* k_Wl  = (const float*)d_in[22];
    const float* k_bl  = (const float*)d_in[23];
    const float* k_Wr  = (const float*)d_in[24];
    const float* k_br  = (const float*)d_in[25];
    const float* k_att = (const float*)d_in[26];
    const float* k_b   = (const float*)d_in[27];
    const float* kln_g = (const float*)d_in[28];
    const float* kln_b = (const float*)d_in[29];
    const float* kh_W  = (const float*)d_in[30];
    const float* kh_b  = (const float*)d_in[31];

    int N = in_sizes[0] / 128;
    int E = in_sizes[1] / 2;
    float* out = (float*)d_out;

    float *h1, *h2, *biasc;
    __half *xlxr, *xlxr2;
    __nv_bfloat16 *ahi, *alo, *wthi, *wtlo;
    cudaGetSymbolAddress((void**)&h1, g_h1);
    cudaGetSymbolAddress((void**)&h2, g_h2);
    cudaGetSymbolAddress((void**)&xlxr, g_xlxr);
    cudaGetSymbolAddress((void**)&xlxr2, g_xlxr2);
    cudaGetSymbolAddress((void**)&biasc, g_biasc);
    cudaGetSymbolAddress((void**)&ahi, g_ahi);
    cudaGetSymbolAddress((void**)&alo, g_alo);
    cudaGetSymbolAddress((void**)&wthi, g_wthi);
    cudaGetSymbolAddress((void**)&wtlo, g_wtlo);

    cudaFuncSetAttribute(gemm_mma_k, cudaFuncAttributeMaxDynamicSharedMemorySize, GMM_SMEM);

    const int NOSPLIT = 1 << 30;
    int prep_threads = N * 32;                 // dominated by x conversion
    if (prep_threads < E) prep_threads = E;

    init_cnt_k<<<(N + 255) / 256, 256>>>(N);                               // 1: SOLE g_cnt init
    prep_k<<<(prep_threads + 255) / 256, 256>>>(                           // 2: count+weights+bias+convA
        W_in, c1_Wl, c1_Wr, a_Wl, a_Wr, k_Wl, k_Wr,
        b_in, c1_bl, c1_br, a_bl, a_br, k_bl, k_br,
        ei + E, E, x, N);
    gemm_mma_k<<<dim3(148, 1), 512, GMM_SMEM>>>(ahi, alo, N,               // 3: input layer
        wthi, wtlo, biasc, h1, (float*)0, NOSPLIT, 128, 1, 1, 0);
    gemm_mma_k<<<dim3(18, 8), 512, GMM_SMEM>>>(ahi, alo, N,                // 4 <- profiled
        wthi + (size_t)128 * 128, wtlo + (size_t)128 * 128, biasc + 128,
        (float*)xlxr, (float*)0, NOSPLIT, 1024, 0, 0, 1);

    scan2_k<<<1, 1024>>>(N);                                               // 5
    scatter_k<<<(E + N + 255) / 256, 256>>>(ei, ei + E, E, N);             // 6

    gat2_k<<<N, 32>>>(xlxr, h1, c1_att, c1_b, ln1_g, ln1_b, h2, N);        // 7

    gemm_mma_k<<<dim3(9, 16), 512, GMM_SMEM>>>(ahi, alo, N,                // 8
        wthi + (size_t)1152 * 128, wtlo + (size_t)1152 * 128, biasc + 1152,
        (float*)xlxr, (float*)xlxr2, 1024, 1024, 0, 0, 1);

    gatf_k<<<N, 32>>>(xlxr, xlxr2, h2,                                     // 9: fused actor+critic
                      a_att, k_att, a_b, k_b,
                      aln_g, aln_b, kln_g, kln_b,
                      ah_W, ah_b, kh_W, kh_b,
                      out, out + N, N);
}